// round 2
// baseline (speedup 1.0000x reference)
#include <cuda_runtime.h>
#include <math.h>

#define NPATCH 8192
#define DIN    384
#define DH     512
#define HSNN   256
#define TOPK   6

// ---------------- scratch (static device allocations; no cudaMalloc) --------
__device__ float g_H [NPATCH * DH];
__device__ float g_EH[NPATCH * DH];
__device__ float g_ET[NPATCH * DH];
__device__ float g_U [NPATCH * DH];
__device__ float g_V [NPATCH * DH];
__device__ float g_G1[NPATCH * HSNN];
__device__ float g_PART[64 * DH];
__device__ float g_MEAN[DH];
__device__ float g_GS[NPATCH];
__device__ float g_AB[NPATCH];
__device__ float g_TOPV[NPATCH * TOPK];
__device__ int   g_TOPI[NPATCH * TOPK];
__device__ float g_P2[64 * DH];

// ---------------- omic SNN branches -----------------------------------------
struct OmicArgs {
    const float* x[6];
    const float* w1[6];
    int s[6];
};

__global__ void omic_kernel(OmicArgs oa, const float* __restrict__ sig_b1,
                            const float* __restrict__ sig_w2,
                            const float* __restrict__ sig_b2,
                            float* __restrict__ out) {
    __shared__ float sx[1536];
    __shared__ float h1[HSNN];
    int br = blockIdx.x, tid = threadIdx.x;
    int s = oa.s[br];
    const float* x = oa.x[br];
    for (int j = tid; j < s; j += 256) sx[j] = x[j];
    __syncthreads();
    const float* w = oa.w1[br] + (size_t)tid * s;
    float acc = sig_b1[br * HSNN + tid];
    for (int j = 0; j < s; j++) acc += w[j] * sx[j];
    h1[tid] = acc > 0.f ? acc : expm1f(acc);
    __syncthreads();
    const float* w2 = sig_w2 + (size_t)br * HSNN * HSNN + (size_t)tid * HSNN;
    float acc2 = sig_b2[br * HSNN + tid];
    #pragma unroll 8
    for (int j = 0; j < HSNN; j++) acc2 += w2[j] * h1[j];
    out[br * HSNN + tid] = acc2 > 0.f ? acc2 : expm1f(acc2);
}

// ---------------- generic NT GEMM: C[i,j] = sum_k A[i,k]*B[j,k] + bias[j] ----
// EPI: 0 = store(bias), 1 = store(leaky(bias+)), 2 = C += leaky(bias+)
template <int EPI>
__global__ void gemm_nt(const float* __restrict__ A, const float* __restrict__ B,
                        const float* __restrict__ bias, float* __restrict__ C,
                        int M, int N, int K) {
    __shared__ float As[16][64];
    __shared__ float Bs[16][64];
    const int bi = blockIdx.y * 64;
    const int bj = blockIdx.x * 64;
    const int tid = threadIdx.x;
    const int tx = tid & 15;       // 0..15 -> 4 cols each
    const int ty = tid >> 4;       // 0..15 -> 4 rows each
    const int lr = tid >> 2;       // 0..63  tile row for loading
    const int lc = (tid & 3) * 4;  // k offset for loading

    float acc[4][4] = {};
    for (int k0 = 0; k0 < K; k0 += 16) {
        float4 a4 = *(const float4*)(A + (size_t)(bi + lr) * K + k0 + lc);
        float4 b4 = *(const float4*)(B + (size_t)(bj + lr) * K + k0 + lc);
        __syncthreads();
        As[lc + 0][lr] = a4.x; As[lc + 1][lr] = a4.y;
        As[lc + 2][lr] = a4.z; As[lc + 3][lr] = a4.w;
        Bs[lc + 0][lr] = b4.x; Bs[lc + 1][lr] = b4.y;
        Bs[lc + 2][lr] = b4.z; Bs[lc + 3][lr] = b4.w;
        __syncthreads();
        #pragma unroll
        for (int k = 0; k < 16; k++) {
            float ar[4], br[4];
            *(float4*)ar = *(const float4*)&As[k][ty * 4];
            *(float4*)br = *(const float4*)&Bs[k][tx * 4];
            #pragma unroll
            for (int ii = 0; ii < 4; ii++)
                #pragma unroll
                for (int jj = 0; jj < 4; jj++)
                    acc[ii][jj] += ar[ii] * br[jj];
        }
    }
    #pragma unroll
    for (int ii = 0; ii < 4; ii++) {
        int i = bi + ty * 4 + ii;
        #pragma unroll
        for (int jj = 0; jj < 4; jj++) {
            int j = bj + tx * 4 + jj;
            float v = acc[ii][jj] + bias[j];
            if (EPI >= 1) v = v >= 0.f ? v : 0.01f * v;
            if (EPI == 2) C[(size_t)i * N + j] += v;
            else          C[(size_t)i * N + j]  = v;
        }
    }
}

// ---------------- column mean of H, then h = 0.5*(h + mean) ------------------
__global__ void colsum_partial(const float* __restrict__ H, float* __restrict__ part) {
    int b = blockIdx.x, tid = threadIdx.x;
    const float* base = H + (size_t)b * 128 * DH;
    float a0 = 0.f, a1 = 0.f;
    for (int r = 0; r < 128; r++) {
        a0 += base[r * DH + tid];
        a1 += base[r * DH + tid + 256];
    }
    part[b * DH + tid] = a0;
    part[b * DH + tid + 256] = a1;
}

__global__ void mean_combine(const float* __restrict__ part, float* __restrict__ mean) {
    int d = threadIdx.x;
    float s = 0.f;
    for (int b = 0; b < 64; b++) s += part[b * DH + d];
    mean[d] = s * (1.f / (float)NPATCH);
}

__global__ void h_update(float* __restrict__ H, const float* __restrict__ mean) {
    int idx = blockIdx.x * 256 + threadIdx.x;
    H[idx] = 0.5f * (H[idx] + mean[idx & (DH - 1)]);
}

// ---------------- fused logits GEMM + per-row top-6 --------------------------
// grid: 128 blocks (64 rows each), 256 threads, BN=128 column tiles.
#define LSTRIDE 129
#define LT_SMEM (DH * 64 * 4 + 16 * 128 * 4 + 64 * LSTRIDE * 4)

__global__ void logits_topk(const float* __restrict__ EH, const float* __restrict__ ET,
                            float* __restrict__ topv, int* __restrict__ topi) {
    extern __shared__ float sm[];
    float* As = sm;                   // [DH][64], k-major
    float* Bs = As + DH * 64;         // [16][128]
    float* Ls = Bs + 16 * 128;        // [64][LSTRIDE]
    const int tid = threadIdx.x;
    const int bi = blockIdx.x * 64;
    const int tx = tid & 15;          // 8 cols each -> 128
    const int ty = tid >> 4;          // 4 rows each -> 64

    // one-time load of the 64x512 e_h slab, transposed to k-major
    for (int q = tid; q < 64 * (DH / 4); q += 256) {
        int r = q >> 7;
        int k = (q & 127) * 4;
        float4 a4 = *(const float4*)(EH + (size_t)(bi + r) * DH + k);
        As[(k + 0) * 64 + r] = a4.x; As[(k + 1) * 64 + r] = a4.y;
        As[(k + 2) * 64 + r] = a4.z; As[(k + 3) * 64 + r] = a4.w;
    }
    float tv[TOPK]; int ti[TOPK];
    #pragma unroll
    for (int k = 0; k < TOPK; k++) { tv[k] = -INFINITY; ti[k] = 0; }
    __syncthreads();

    const float scale = 0.04419417382415922f;  // 512^-0.5
    for (int bj = 0; bj < NPATCH; bj += 128) {
        float acc[4][8] = {};
        for (int k0 = 0; k0 < DH; k0 += 16) {
            __syncthreads();
            #pragma unroll
            for (int q = tid; q < 512; q += 256) {
                int r = q >> 2;
                int kk = (q & 3) * 4;
                float4 b4 = *(const float4*)(ET + (size_t)(bj + r) * DH + k0 + kk);
                Bs[(kk + 0) * 128 + r] = b4.x; Bs[(kk + 1) * 128 + r] = b4.y;
                Bs[(kk + 2) * 128 + r] = b4.z; Bs[(kk + 3) * 128 + r] = b4.w;
            }
            __syncthreads();
            #pragma unroll
            for (int k = 0; k < 16; k++) {
                float a[4], b[8];
                *(float4*)a       = *(const float4*)&As[(k0 + k) * 64 + ty * 4];
                *(float4*)&b[0]   = *(const float4*)&Bs[k * 128 + tx * 8];
                *(float4*)&b[4]   = *(const float4*)&Bs[k * 128 + tx * 8 + 4];
                #pragma unroll
                for (int ii = 0; ii < 4; ii++)
                    #pragma unroll
                    for (int jj = 0; jj < 8; jj++)
                        acc[ii][jj] += a[ii] * b[jj];
            }
        }
        __syncthreads();   // previous scan finished before Ls overwrite
        #pragma unroll
        for (int ii = 0; ii < 4; ii++)
            #pragma unroll
            for (int jj = 0; jj < 8; jj++)
                Ls[(ty * 4 + ii) * LSTRIDE + tx * 8 + jj] = acc[ii][jj] * scale;
        __syncthreads();
        if (tid < 64) {
            const float* row = &Ls[tid * LSTRIDE];
            for (int j = 0; j < 128; j++) {
                float v = row[j];
                if (v > tv[TOPK - 1]) {
                    int pos = TOPK - 1;
                    #pragma unroll
                    for (int q = TOPK - 1; q > 0; q--) {
                        if (v > tv[q - 1]) { tv[q] = tv[q - 1]; ti[q] = ti[q - 1]; pos = q - 1; }
                    }
                    tv[pos] = v; ti[pos] = bj + j;
                }
            }
        }
    }
    if (tid < 64) {
        #pragma unroll
        for (int k = 0; k < TOPK; k++) {
            topv[(size_t)(bi + tid) * TOPK + k] = tv[k];
            topi[(size_t)(bi + tid) * TOPK + k] = ti[k];
        }
    }
}

// ---------------- per-row kNN aggregation: U = e_h+e_Nh, V = e_h*e_Nh --------
__global__ void knn_epi(const float* __restrict__ EH, const float* __restrict__ ET,
                        const float* __restrict__ topv, const int* __restrict__ topi,
                        float* __restrict__ U, float* __restrict__ V) {
    __shared__ float sred[8];
    __shared__ float sNb[TOPK], sGate[TOPK];
    const int i = blockIdx.x, tid = threadIdx.x;  // 128 threads

    float vals[TOPK], p[TOPK];
    #pragma unroll
    for (int k = 0; k < TOPK; k++) vals[k] = topv[(size_t)i * TOPK + k];
    float m = vals[0];
    #pragma unroll
    for (int k = 1; k < TOPK; k++) m = fmaxf(m, vals[k]);
    float se = 0.f;
    #pragma unroll
    for (int k = 0; k < TOPK; k++) { p[k] = expf(vals[k] - m); se += p[k]; }
    float inv = 1.f / se;
    #pragma unroll
    for (int k = 0; k < TOPK; k++) p[k] *= inv;

    float eh[4];
    #pragma unroll
    for (int c = 0; c < 4; c++) eh[c] = EH[(size_t)i * DH + tid + 128 * c];

    float Nb[TOPK][4];
    for (int k = 0; k < TOPK; k++) {
        const float* et = ET + (size_t)topi[(size_t)i * TOPK + k] * DH;
        float sN = 0.f, sG = 0.f;
        #pragma unroll
        for (int c = 0; c < 4; c++) {
            float nb = et[tid + 128 * c];
            Nb[k][c] = nb;
            float ehr = p[k] * nb + (1.f - p[k]) * eh[c];
            sN += nb;
            sG += tanhf(eh[c] + ehr);
        }
        #pragma unroll
        for (int off = 16; off; off >>= 1) {
            sN += __shfl_down_sync(0xffffffffu, sN, off);
            sG += __shfl_down_sync(0xffffffffu, sG, off);
        }
        if ((tid & 31) == 0) { sred[tid >> 5] = sN; sred[4 + (tid >> 5)] = sG; }
        __syncthreads();
        if (tid == 0) {
            float a = 0.f, b = 0.f;
            for (int w = 0; w < 4; w++) { a += sred[w]; b += sred[4 + w]; }
            sNb[k] = a; sGate[k] = b;
        }
        __syncthreads();
    }
    float ka[TOPK], kp[TOPK];
    #pragma unroll
    for (int k = 0; k < TOPK; k++) ka[k] = sNb[k] * sGate[k];
    m = ka[0];
    #pragma unroll
    for (int k = 1; k < TOPK; k++) m = fmaxf(m, ka[k]);
    se = 0.f;
    #pragma unroll
    for (int k = 0; k < TOPK; k++) { kp[k] = expf(ka[k] - m); se += kp[k]; }
    inv = 1.f / se;
    float enh[4] = {0.f, 0.f, 0.f, 0.f};
    #pragma unroll
    for (int k = 0; k < TOPK; k++)
        #pragma unroll
        for (int c = 0; c < 4; c++) enh[c] += kp[k] * inv * Nb[k][c];
    #pragma unroll
    for (int c = 0; c < 4; c++) {
        size_t o = (size_t)i * DH + tid + 128 * c;
        U[o] = eh[c] + enh[c];
        V[o] = eh[c] * enh[c];
    }
}

// ---------------- attention readout ------------------------------------------
__global__ void att_score(const float* __restrict__ G1, const float* __restrict__ aw2,
                          const float* __restrict__ ab2, float* __restrict__ Gs) {
    int warp = threadIdx.x >> 5, lane = threadIdx.x & 31;
    int row = blockIdx.x * 8 + warp;
    float s = 0.f;
    #pragma unroll
    for (int c = 0; c < 8; c++) {
        int j = lane + 32 * c;
        s += G1[(size_t)row * HSNN + j] * aw2[j];
    }
    #pragma unroll
    for (int off = 16; off; off >>= 1) s += __shfl_down_sync(0xffffffffu, s, off);
    if (lane == 0) Gs[row] = s + ab2[0];
}

__global__ void softmax_n(const float* __restrict__ Gs, float* __restrict__ A) {
    __shared__ float sm[32];
    int tid = threadIdx.x;  // 1024
    int lane = tid & 31, warp = tid >> 5;
    float v[8], m = -INFINITY;
    #pragma unroll
    for (int c = 0; c < 8; c++) { v[c] = Gs[tid + 1024 * c]; m = fmaxf(m, v[c]); }
    #pragma unroll
    for (int off = 16; off; off >>= 1) m = fmaxf(m, __shfl_xor_sync(0xffffffffu, m, off));
    if (lane == 0) sm[warp] = m;
    __syncthreads();
    if (tid < 32) {
        float t = sm[tid];
        #pragma unroll
        for (int off = 16; off; off >>= 1) t = fmaxf(t, __shfl_xor_sync(0xffffffffu, t, off));
        if (tid == 0) sm[0] = t;
    }
    __syncthreads();
    m = sm[0];
    __syncthreads();
    float e[8], s = 0.f;
    #pragma unroll
    for (int c = 0; c < 8; c++) { e[c] = expf(v[c] - m); s += e[c]; }
    #pragma unroll
    for (int off = 16; off; off >>= 1) s += __shfl_xor_sync(0xffffffffu, s, off);
    if (lane == 0) sm[warp] = s;
    __syncthreads();
    if (tid < 32) {
        float t = sm[tid];
        #pragma unroll
        for (int off = 16; off; off >>= 1) t += __shfl_xor_sync(0xffffffffu, t, off);
        if (tid == 0) sm[0] = t;
    }
    __syncthreads();
    float inv = 1.f / sm[0];
    #pragma unroll
    for (int c = 0; c < 8; c++) A[tid + 1024 * c] = e[c] * inv;
}

__global__ void eg_partial(const float* __restrict__ A, const float* __restrict__ X,
                           float* __restrict__ P2) {
    int b = blockIdx.x, tid = threadIdx.x;
    float a0 = 0.f, a1 = 0.f;
    for (int r = 0; r < 128; r++) {
        int n = b * 128 + r;
        float a = A[n];
        a0 += a * X[(size_t)n * DH + tid];
        a1 += a * X[(size_t)n * DH + tid + 256];
    }
    P2[b * DH + tid] = a0;
    P2[b * DH + tid + 256] = a1;
}

__global__ void eg_combine(const float* __restrict__ P2, float* __restrict__ eg) {
    int d = threadIdx.x;
    float s = 0.f;
    for (int b = 0; b < 64; b++) s += P2[b * DH + d];
    eg[d] = s;
}

// ---------------- host ------------------------------------------------------
extern "C" void kernel_launch(void* const* d_in, const int* in_sizes, int n_in,
                              void* d_out, int out_size) {
    const float *xo[6], *w1[6];
    int s6[6];
    const float *x_path, *sig_b1, *sig_w2, *sig_b2;

    // detect input ordering: dict-insertion order puts x_path (3145728) at idx 12
    bool dictOrder = (in_sizes[12] == NPATCH * DIN);
    if (dictOrder) {
        for (int i = 0; i < 6; i++) {
            xo[i] = (const float*)d_in[2 * i];
            w1[i] = (const float*)d_in[2 * i + 1];
            s6[i] = in_sizes[2 * i];
        }
        x_path = (const float*)d_in[12];
        sig_b1 = (const float*)d_in[13];
        sig_w2 = (const float*)d_in[14];
        sig_b2 = (const float*)d_in[15];
    } else {
        for (int i = 0; i < 6; i++) {
            xo[i] = (const float*)d_in[i];
            w1[i] = (const float*)d_in[6 + i];
            s6[i] = in_sizes[i];
        }
        sig_b1 = (const float*)d_in[12];
        sig_w2 = (const float*)d_in[13];
        sig_b2 = (const float*)d_in[14];
        x_path = (const float*)d_in[15];
    }
    const float* fc1_w = (const float*)d_in[16];
    const float* fc1_b = (const float*)d_in[17];
    const float* wh_w  = (const float*)d_in[18];
    const float* wh_b  = (const float*)d_in[19];
    const float* wt_w  = (const float*)d_in[20];
    const float* wt_b  = (const float*)d_in[21];
    const float* l1w   = (const float*)d_in[22];
    const float* l1b   = (const float*)d_in[23];
    const float* l2w   = (const float*)d_in[24];
    const float* l2b   = (const float*)d_in[25];
    const float* aw1   = (const float*)d_in[26];
    const float* ab1   = (const float*)d_in[27];
    const float* aw2   = (const float*)d_in[28];
    const float* ab2   = (const float*)d_in[29];

    float* out     = (float*)d_out;
    float* out_eh2 = out + 6 * HSNN;
    float* out_eg  = out + 6 * HSNN + NPATCH * DH;

    float *H, *EH, *ET, *U, *V, *G1, *PART, *MEAN, *GS, *AB, *TOPV, *P2;
    int* TOPI;
    cudaGetSymbolAddress((void**)&H,    g_H);
    cudaGetSymbolAddress((void**)&EH,   g_EH);
    cudaGetSymbolAddress((void**)&ET,   g_ET);
    cudaGetSymbolAddress((void**)&U,    g_U);
    cudaGetSymbolAddress((void**)&V,    g_V);
    cudaGetSymbolAddress((void**)&G1,   g_G1);
    cudaGetSymbolAddress((void**)&PART, g_PART);
    cudaGetSymbolAddress((void**)&MEAN, g_MEAN);
    cudaGetSymbolAddress((void**)&GS,   g_GS);
    cudaGetSymbolAddress((void**)&AB,   g_AB);
    cudaGetSymbolAddress((void**)&TOPV, g_TOPV);
    cudaGetSymbolAddress((void**)&TOPI, g_TOPI);
    cudaGetSymbolAddress((void**)&P2,   g_P2);

    OmicArgs oa;
    for (int i = 0; i < 6; i++) { oa.x[i] = xo[i]; oa.w1[i] = w1[i]; oa.s[i] = s6[i]; }

    // 1) omic branches -> out[0:1536]
    omic_kernel<<<6, 256>>>(oa, sig_b1, sig_w2, sig_b2, out);

    // 2) h0 = leaky(x_path @ fc1_w^T + b)
    gemm_nt<1><<<dim3(DH / 64, NPATCH / 64), 256>>>(x_path, fc1_w, fc1_b, H, NPATCH, DH, DIN);

    // 3) h = 0.5*(h0 + colmean(h0))
    colsum_partial<<<64, 256>>>(H, PART);
    mean_combine<<<1, 512>>>(PART, MEAN);
    h_update<<<NPATCH * DH / 256, 256>>>(H, MEAN);

    // 4) e_h, e_t
    gemm_nt<0><<<dim3(DH / 64, NPATCH / 64), 256>>>(H, wh_w, wh_b, EH, NPATCH, DH, DH);
    gemm_nt<0><<<dim3(DH / 64, NPATCH / 64), 256>>>(H, wt_w, wt_b, ET, NPATCH, DH, DH);

    // 5) fused logits + top-6
    cudaFuncSetAttribute(logits_topk, cudaFuncAttributeMaxDynamicSharedMemorySize, LT_SMEM);
    logits_topk<<<NPATCH / 64, 256, LT_SMEM>>>(EH, ET, TOPV, TOPI);

    // 6) kNN aggregation -> U = e_h + e_Nh, V = e_h * e_Nh
    knn_epi<<<NPATCH, 128>>>(EH, ET, TOPV, TOPI, U, V);

    // 7) e_h2 = leaky(U@l1^T+b1) + leaky(V@l2^T+b2)  -> out
    gemm_nt<1><<<dim3(DH / 64, NPATCH / 64), 256>>>(U, l1w, l1b, out_eh2, NPATCH, DH, DH);
    gemm_nt<2><<<dim3(DH / 64, NPATCH / 64), 256>>>(V, l2w, l2b, out_eh2, NPATCH, DH, DH);

    // 8) attention readout -> e_g
    gemm_nt<1><<<dim3(HSNN / 64, NPATCH / 64), 256>>>(out_eh2, aw1, ab1, G1, NPATCH, HSNN, DH);
    att_score<<<NPATCH / 8, 256>>>(G1, aw2, ab2, GS);
    softmax_n<<<1, 1024>>>(GS, AB);
    eg_partial<<<64, 256>>>(AB, out_eh2, P2);
    eg_combine<<<1, 512>>>(P2, out_eg);
}

// round 6
// speedup vs baseline: 1.0927x; 1.0927x over previous
#include <cuda_runtime.h>
#include <math.h>

#define NPATCH 8192
#define DIN    384
#define DH     512
#define HSNN   256
#define TOPK   6

typedef unsigned long long ull;

__device__ __forceinline__ void ffma2(ull& d, ull a, ull b) {
    asm("fma.rn.f32x2 %0, %1, %2, %0;" : "+l"(d) : "l"(a), "l"(b));
}
__device__ __forceinline__ float psum(ull v) {
    float lo = __uint_as_float((unsigned)(v & 0xffffffffu));
    float hi = __uint_as_float((unsigned)(v >> 32));
    return lo + hi;
}

// ---------------- scratch (static device allocations; no cudaMalloc) --------
__device__ float g_H [NPATCH * DH];
__device__ float g_EH[NPATCH * DH];
__device__ float g_ET[NPATCH * DH];
__device__ float g_U [NPATCH * DH];
__device__ float g_V [NPATCH * DH];
__device__ float g_G1[NPATCH * HSNN];
__device__ float g_PART[64 * DH];
__device__ float g_MEAN[DH];
__device__ float g_GS[NPATCH];
__device__ float g_AB[NPATCH];
__device__ float g_TOPV[NPATCH * TOPK];
__device__ int   g_TOPI[NPATCH * TOPK];
__device__ float g_P2[64 * DH];

// ---------------- omic SNN branches -----------------------------------------
struct OmicArgs {
    const float* x[6];
    const float* w1[6];
    int s[6];
};

__global__ void omic_kernel(OmicArgs oa, const float* __restrict__ sig_b1,
                            const float* __restrict__ sig_w2,
                            const float* __restrict__ sig_b2,
                            float* __restrict__ out) {
    __shared__ float sx[1536];
    __shared__ float h1[HSNN];
    int br = blockIdx.x, tid = threadIdx.x;
    int s = oa.s[br];
    const float* x = oa.x[br];
    for (int j = tid; j < s; j += 256) sx[j] = x[j];
    __syncthreads();
    const float* w = oa.w1[br] + (size_t)tid * s;
    float acc = sig_b1[br * HSNN + tid];
    for (int j = 0; j < s; j++) acc += w[j] * sx[j];
    h1[tid] = acc > 0.f ? acc : expm1f(acc);
    __syncthreads();
    const float* w2 = sig_w2 + (size_t)br * HSNN * HSNN + (size_t)tid * HSNN;
    float acc2 = sig_b2[br * HSNN + tid];
    #pragma unroll 8
    for (int j = 0; j < HSNN; j++) acc2 += w2[j] * h1[j];
    out[br * HSNN + tid] = acc2 > 0.f ? acc2 : expm1f(acc2);
}

// ---------------- packed (FFMA2) NT GEMM ------------------------------------
// C[i,j] = sum_k A[i,k]*B[j,k] + bias[j]
// EPI: 0 = store(bias), 1 = store(leaky(bias+)), 2 = C += leaky(bias+)
template <int EPI>
__global__ void gemm_nt(const float* __restrict__ A, const float* __restrict__ B,
                        const float* __restrict__ bias, float* __restrict__ C,
                        int M, int N, int K) {
    __shared__ float As2[8 * 128 + 32];
    __shared__ float Bs2[8 * 128 + 32];
    const int bi = blockIdx.y * 64;
    const int bj = blockIdx.x * 64;
    const int tid = threadIdx.x;
    const int tx = tid & 15;
    const int ty = tid >> 4;
    const int lr = tid >> 2;         // 0..63 tile row for loading
    const int lk = (tid & 3) * 4;    // k offset for loading

    ull acc[4][4] = {};
    for (int k0 = 0; k0 < K; k0 += 16) {
        float4 a4 = *(const float4*)(A + (size_t)(bi + lr) * K + k0 + lk);
        float4 b4 = *(const float4*)(B + (size_t)(bj + lr) * K + k0 + lk);
        __syncthreads();
        int k2a = lk >> 1;
        *(float2*)&As2[k2a * 128 + (k2a & 7) * 4 + lr * 2] = make_float2(a4.x, a4.y);
        *(float2*)&As2[(k2a + 1) * 128 + ((k2a + 1) & 7) * 4 + lr * 2] = make_float2(a4.z, a4.w);
        *(float2*)&Bs2[k2a * 128 + (k2a & 7) * 4 + lr * 2] = make_float2(b4.x, b4.y);
        *(float2*)&Bs2[(k2a + 1) * 128 + ((k2a + 1) & 7) * 4 + lr * 2] = make_float2(b4.z, b4.w);
        __syncthreads();
        #pragma unroll
        for (int k2 = 0; k2 < 8; k2++) {
            const float* ab = As2 + k2 * 128 + (k2 & 7) * 4;
            const float* bb = Bs2 + k2 * 128 + (k2 & 7) * 4 + tx * 2;
            ulonglong2 a01 = *(const ulonglong2*)(ab + ty * 8);
            ulonglong2 a23 = *(const ulonglong2*)(ab + ty * 8 + 4);
            #pragma unroll
            for (int c = 0; c < 4; c++) {
                ull bv = *(const ull*)(bb + c * 32);
                ffma2(acc[0][c], a01.x, bv);
                ffma2(acc[1][c], a01.y, bv);
                ffma2(acc[2][c], a23.x, bv);
                ffma2(acc[3][c], a23.y, bv);
            }
        }
    }
    #pragma unroll
    for (int ii = 0; ii < 4; ii++) {
        int i = bi + ty * 4 + ii;
        #pragma unroll
        for (int c = 0; c < 4; c++) {
            int j = bj + tx + 16 * c;
            float v = psum(acc[ii][c]) + bias[j];
            if (EPI >= 1) v = v >= 0.f ? v : 0.01f * v;
            if (EPI == 2) C[(size_t)i * N + j] += v;
            else          C[(size_t)i * N + j]  = v;
        }
    }
}

// ---------------- column mean of H, then h = 0.5*(h + mean) ------------------
__global__ void colsum_partial(const float* __restrict__ H, float* __restrict__ part) {
    int b = blockIdx.x, tid = threadIdx.x;
    const float* base = H + (size_t)b * 128 * DH;
    float a0 = 0.f, a1 = 0.f;
    for (int r = 0; r < 128; r++) {
        a0 += base[r * DH + tid];
        a1 += base[r * DH + tid + 256];
    }
    part[b * DH + tid] = a0;
    part[b * DH + tid + 256] = a1;
}

__global__ void mean_combine(const float* __restrict__ part, float* __restrict__ mean) {
    int d = threadIdx.x;
    float s = 0.f;
    for (int b = 0; b < 64; b++) s += part[b * DH + d];
    mean[d] = s * (1.f / (float)NPATCH);
}

__global__ void h_update(float* __restrict__ H, const float* __restrict__ mean) {
    int idx = blockIdx.x * 256 + threadIdx.x;
    H[idx] = 0.5f * (H[idx] + mean[idx & (DH - 1)]);
}

// ---------------- fused logits GEMM (FFMA2) + per-row top-6 ------------------
#define LSTRIDE 129
#define BSTILE  2080
#define LT_AS   (256 * 128)
#define LT_BS   (2 * BSTILE)
#define LT_LS   (64 * LSTRIDE)
#define LT_MV   (64 * 4 * TOPK)
#define LT_SMEM ((LT_AS + LT_BS + LT_LS + 2 * LT_MV) * 4)

__device__ __forceinline__ void fill_b_tile(float* __restrict__ dst,
                                            const float* __restrict__ ET,
                                            int bj, int k0, int tid) {
    #pragma unroll
    for (int it = 0; it < 2; it++) {
        int u = tid + it * 256;
        int r = u >> 2, kk = (u & 3) * 4;
        float4 b4 = *(const float4*)(ET + (size_t)(bj + r) * DH + k0 + kk);
        int k2a = kk >> 1;
        *(float2*)&dst[k2a * 256 + (k2a & 7) * 4 + r * 2] = make_float2(b4.x, b4.y);
        *(float2*)&dst[(k2a + 1) * 256 + ((k2a + 1) & 7) * 4 + r * 2] = make_float2(b4.z, b4.w);
    }
}

__global__ __launch_bounds__(256, 1)
void logits_topk(const float* __restrict__ EH, const float* __restrict__ ET,
                 float* __restrict__ topv, int* __restrict__ topi) {
    extern __shared__ float sm[];
    float* As2 = sm;
    float* Bs2 = As2 + LT_AS;
    float* Ls  = Bs2 + LT_BS;
    float* mv  = Ls + LT_LS;
    int*   mi  = (int*)(mv + LT_MV);
    const int tid = threadIdx.x;
    const int bi = blockIdx.x * 64;
    const int tx = tid & 15;
    const int ty = tid >> 4;

    // one-time load of the 64x512 e_h slab, k-pair interleaved
    for (int u = tid; u < 64 * 128; u += 256) {
        int k4 = u & 127, r = u >> 7;
        float4 a4 = *(const float4*)(EH + (size_t)(bi + r) * DH + k4 * 4);
        int k2a = k4 * 2;
        *(float2*)&As2[k2a * 128 + r * 2] = make_float2(a4.x, a4.y);
        *(float2*)&As2[(k2a + 1) * 128 + r * 2] = make_float2(a4.z, a4.w);
    }
    float tv[TOPK]; int ti[TOPK];
    #pragma unroll
    for (int k = 0; k < TOPK; k++) { tv[k] = -INFINITY; ti[k] = 0; }

    const float scale = 0.04419417382415922f;  // 512^-0.5
    for (int bj = 0; bj < NPATCH; bj += 128) {
        ull acc[4][8] = {};
        fill_b_tile(Bs2, ET, bj, 0, tid);
        __syncthreads();
        for (int ch = 0; ch < 32; ch++) {
            const float* cur = Bs2 + (ch & 1) * BSTILE;
            if (ch < 31) fill_b_tile(Bs2 + ((ch + 1) & 1) * BSTILE, ET, bj, (ch + 1) * 16, tid);
            int kb2 = ch * 8;
            #pragma unroll
            for (int k2 = 0; k2 < 8; k2++) {
                ulonglong2 a01 = *(const ulonglong2*)&As2[(kb2 + k2) * 128 + ty * 8];
                ulonglong2 a23 = *(const ulonglong2*)&As2[(kb2 + k2) * 128 + ty * 8 + 4];
                const float* bb = cur + k2 * 256 + (k2 & 7) * 4 + tx * 2;
                #pragma unroll
                for (int c = 0; c < 8; c++) {
                    ull bv = *(const ull*)(bb + c * 32);
                    ffma2(acc[0][c], a01.x, bv);
                    ffma2(acc[1][c], a01.y, bv);
                    ffma2(acc[2][c], a23.x, bv);
                    ffma2(acc[3][c], a23.y, bv);
                }
            }
            __syncthreads();
        }
        // write scaled logits to smem
        #pragma unroll
        for (int ii = 0; ii < 4; ii++)
            #pragma unroll
            for (int c = 0; c < 8; c++)
                Ls[(ty * 4 + ii) * LSTRIDE + tx + 16 * c] = psum(acc[ii][c]) * scale;
        __syncthreads();
        // parallel local top-6: 4 threads/row, bank-staggered 32-col blocks
        {
            int srow = tid >> 2, q = tid & 3;
            float lv[TOPK]; int li[TOPK];
            #pragma unroll
            for (int k = 0; k < TOPK; k++) { lv[k] = -INFINITY; li[k] = 0; }
            const float* rp = Ls + srow * LSTRIDE + q * 32;
            for (int t = 0; t < 32; t++) {
                int cc = (t + q * 8) & 31;
                float v = rp[cc];
                if (v > lv[TOPK - 1]) {
                    int pos = TOPK - 1;
                    #pragma unroll
                    for (int kq = TOPK - 1; kq > 0; kq--)
                        if (v > lv[kq - 1]) { lv[kq] = lv[kq - 1]; li[kq] = li[kq - 1]; pos = kq - 1; }
                    lv[pos] = v; li[pos] = bj + q * 32 + cc;
                }
            }
            #pragma unroll
            for (int k = 0; k < TOPK; k++) {
                mv[(srow * 4 + q) * TOPK + k] = lv[k];
                mi[(srow * 4 + q) * TOPK + k] = li[k];
            }
        }
        __syncthreads();
        if (tid < 64) {
            for (int s = 0; s < 4 * TOPK; s++) {
                float v = mv[tid * 4 * TOPK + s];
                int  ix = mi[tid * 4 * TOPK + s];
                if (v > tv[TOPK - 1]) {
                    int pos = TOPK - 1;
                    #pragma unroll
                    for (int kq = TOPK - 1; kq > 0; kq--)
                        if (v > tv[kq - 1]) { tv[kq] = tv[kq - 1]; ti[kq] = ti[kq - 1]; pos = kq - 1; }
                    tv[pos] = v; ti[pos] = ix;
                }
            }
        }
    }
    if (tid < 64) {
        #pragma unroll
        for (int k = 0; k < TOPK; k++) {
            topv[(size_t)(bi + tid) * TOPK + k] = tv[k];
            topi[(size_t)(bi + tid) * TOPK + k] = ti[k];
        }
    }
}

// ---------------- per-row kNN aggregation: U = e_h+e_Nh, V = e_h*e_Nh --------
__global__ void knn_epi(const float* __restrict__ EH, const float* __restrict__ ET,
                        const float* __restrict__ topv, const int* __restrict__ topi,
                        float* __restrict__ U, float* __restrict__ V) {
    __shared__ float sred[8];
    __shared__ float sNb[TOPK], sGate[TOPK];
    const int i = blockIdx.x, tid = threadIdx.x;  // 128 threads

    float vals[TOPK], p[TOPK];
    #pragma unroll
    for (int k = 0; k < TOPK; k++) vals[k] = topv[(size_t)i * TOPK + k];
    float m = vals[0];
    #pragma unroll
    for (int k = 1; k < TOPK; k++) m = fmaxf(m, vals[k]);
    float se = 0.f;
    #pragma unroll
    for (int k = 0; k < TOPK; k++) { p[k] = expf(vals[k] - m); se += p[k]; }
    float inv = 1.f / se;
    #pragma unroll
    for (int k = 0; k < TOPK; k++) p[k] *= inv;

    float eh[4];
    #pragma unroll
    for (int c = 0; c < 4; c++) eh[c] = EH[(size_t)i * DH + tid + 128 * c];

    float Nb[TOPK][4];
    for (int k = 0; k < TOPK; k++) {
        const float* et = ET + (size_t)topi[(size_t)i * TOPK + k] * DH;
        float sN = 0.f, sG = 0.f;
        #pragma unroll
        for (int c = 0; c < 4; c++) {
            float nb = et[tid + 128 * c];
            Nb[k][c] = nb;
            float ehr = p[k] * nb + (1.f - p[k]) * eh[c];
            sN += nb;
            sG += tanhf(eh[c] + ehr);
        }
        #pragma unroll
        for (int off = 16; off; off >>= 1) {
            sN += __shfl_down_sync(0xffffffffu, sN, off);
            sG += __shfl_down_sync(0xffffffffu, sG, off);
        }
        if ((tid & 31) == 0) { sred[tid >> 5] = sN; sred[4 + (tid >> 5)] = sG; }
        __syncthreads();
        if (tid == 0) {
            float a = 0.f, b = 0.f;
            for (int w = 0; w < 4; w++) { a += sred[w]; b += sred[4 + w]; }
            sNb[k] = a; sGate[k] = b;
        }
        __syncthreads();
    }
    float ka[TOPK], kp[TOPK];
    #pragma unroll
    for (int k = 0; k < TOPK; k++) ka[k] = sNb[k] * sGate[k];
    m = ka[0];
    #pragma unroll
    for (int k = 1; k < TOPK; k++) m = fmaxf(m, ka[k]);
    se = 0.f;
    #pragma unroll
    for (int k = 0; k < TOPK; k++) { kp[k] = expf(ka[k] - m); se += kp[k]; }
    inv = 1.f / se;
    float enh[4] = {0.f, 0.f, 0.f, 0.f};
    #pragma unroll
    for (int k = 0; k < TOPK; k++)
        #pragma unroll
        for (int c = 0; c < 4; c++) enh[c] += kp[k] * inv * Nb[k][c];
    #pragma unroll
    for (int c = 0; c < 4; c++) {
        size_t o = (size_t)i * DH + tid + 128 * c;
        U[o] = eh[c] + enh[c];
        V[o] = eh[c] * enh[c];
    }
}

// ---------------- attention readout ------------------------------------------
__global__ void att_score(const float* __restrict__ G1, const float* __restrict__ aw2,
                          const float* __restrict__ ab2, float* __restrict__ Gs) {
    int warp = threadIdx.x >> 5, lane = threadIdx.x & 31;
    int row = blockIdx.x * 8 + warp;
    float s = 0.f;
    #pragma unroll
    for (int c = 0; c < 8; c++) {
        int j = lane + 32 * c;
        s += G1[(size_t)row * HSNN + j] * aw2[j];
    }
    #pragma unroll
    for (int off = 16; off; off >>= 1) s += __shfl_down_sync(0xffffffffu, s, off);
    if (lane == 0) Gs[row] = s + ab2[0];
}

__global__ void softmax_n(const float* __restrict__ Gs, float* __restrict__ A) {
    __shared__ float sm[32];
    int tid = threadIdx.x;  // 1024
    int lane = tid & 31, warp = tid >> 5;
    float v[8], m = -INFINITY;
    #pragma unroll
    for (int c = 0; c < 8; c++) { v[c] = Gs[tid + 1024 * c]; m = fmaxf(m, v[c]); }
    #pragma unroll
    for (int off = 16; off; off >>= 1) m = fmaxf(m, __shfl_xor_sync(0xffffffffu, m, off));
    if (lane == 0) sm[warp] = m;
    __syncthreads();
    if (tid < 32) {
        float t = sm[tid];
        #pragma unroll
        for (int off = 16; off; off >>= 1) t = fmaxf(t, __shfl_xor_sync(0xffffffffu, t, off));
        if (tid == 0) sm[0] = t;
    }
    __syncthreads();
    m = sm[0];
    __syncthreads();
    float e[8], s = 0.f;
    #pragma unroll
    for (int c = 0; c < 8; c++) { e[c] = expf(v[c] - m); s += e[c]; }
    #pragma unroll
    for (int off = 16; off; off >>= 1) s += __shfl_xor_sync(0xffffffffu, s, off);
    if (lane == 0) sm[warp] = s;
    __syncthreads();
    if (tid < 32) {
        float t = sm[tid];
        #pragma unroll
        for (int off = 16; off; off >>= 1) t += __shfl_xor_sync(0xffffffffu, t, off);
        if (tid == 0) sm[0] = t;
    }
    __syncthreads();
    float inv = 1.f / sm[0];
    #pragma unroll
    for (int c = 0; c < 8; c++) A[tid + 1024 * c] = e[c] * inv;
}

__global__ void eg_partial(const float* __restrict__ A, const float* __restrict__ X,
                           float* __restrict__ P2) {
    int b = blockIdx.x, tid = threadIdx.x;
    float a0 = 0.f, a1 = 0.f;
    for (int r = 0; r < 128; r++) {
        int n = b * 128 + r;
        float a = A[n];
        a0 += a * X[(size_t)n * DH + tid];
        a1 += a * X[(size_t)n * DH + tid + 256];
    }
    P2[b * DH + tid] = a0;
    P2[b * DH + tid + 256] = a1;
}

__global__ void eg_combine(const float* __restrict__ P2, float* __restrict__ eg) {
    int d = threadIdx.x;
    float s = 0.f;
    for (int b = 0; b < 64; b++) s += P2[b * DH + d];
    eg[d] = s;
}

// ---------------- host ------------------------------------------------------
extern "C" void kernel_launch(void* const* d_in, const int* in_sizes, int n_in,
                              void* d_out, int out_size) {
    const float *xo[6], *w1[6];
    int s6[6];
    const float *x_path, *sig_b1, *sig_w2, *sig_b2;

    bool dictOrder = (in_sizes[12] == NPATCH * DIN);
    if (dictOrder) {
        for (int i = 0; i < 6; i++) {
            xo[i] = (const float*)d_in[2 * i];
            w1[i] = (const float*)d_in[2 * i + 1];
            s6[i] = in_sizes[2 * i];
        }
        x_path = (const float*)d_in[12];
        sig_b1 = (const float*)d_in[13];
        sig_w2 = (const float*)d_in[14];
        sig_b2 = (const float*)d_in[15];
    } else {
        for (int i = 0; i < 6; i++) {
            xo[i] = (const float*)d_in[i];
            w1[i] = (const float*)d_in[6 + i];
            s6[i] = in_sizes[i];
        }
        sig_b1 = (const float*)d_in[12];
        sig_w2 = (const float*)d_in[13];
        sig_b2 = (const float*)d_in[14];
        x_path = (const float*)d_in[15];
    }
    const float* fc1_w = (const float*)d_in[16];
    const float* fc1_b = (const float*)d_in[17];
    const float* wh_w  = (const float*)d_in[18];
    const float* wh_b  = (const float*)d_in[19];
    const float* wt_w  = (const float*)d_in[20];
    const float* wt_b  = (const float*)d_in[21];
    const float* l1w   = (const float*)d_in[22];
    const float* l1b   = (const float*)d_in[23];
    const float* l2w   = (const float*)d_in[24];
    const float* l2b   = (const float*)d_in[25];
    const float* aw1   = (const float*)d_in[26];
    const float* ab1   = (const float*)d_in[27];
    const float* aw2   = (const float*)d_in[28];
    const float* ab2   = (const float*)d_in[29];

    float* out     = (float*)d_out;
    float* out_eh2 = out + 6 * HSNN;
    float* out_eg  = out + 6 * HSNN + NPATCH * DH;

    float *H, *EH, *ET, *U, *V, *G1, *PART, *MEAN, *GS, *AB, *TOPV, *P2;
    int* TOPI;
    cudaGetSymbolAddress((void**)&H,    g_H);
    cudaGetSymbolAddress((void**)&EH,   g_EH);
    cudaGetSymbolAddress((void**)&ET,   g_ET);
    cudaGetSymbolAddress((void**)&U,    g_U);
    cudaGetSymbolAddress((void**)&V,    g_V);
    cudaGetSymbolAddress((void**)&G1,   g_G1);
    cudaGetSymbolAddress((void**)&PART, g_PART);
    cudaGetSymbolAddress((void**)&MEAN, g_MEAN);
    cudaGetSymbolAddress((void**)&GS,   g_GS);
    cudaGetSymbolAddress((void**)&AB,   g_AB);
    cudaGetSymbolAddress((void**)&TOPV, g_TOPV);
    cudaGetSymbolAddress((void**)&TOPI, g_TOPI);
    cudaGetSymbolAddress((void**)&P2,   g_P2);

    OmicArgs oa;
    for (int i = 0; i < 6; i++) { oa.x[i] = xo[i]; oa.w1[i] = w1[i]; oa.s[i] = s6[i]; }

    // 1) omic branches -> out[0:1536]
    omic_kernel<<<6, 256>>>(oa, sig_b1, sig_w2, sig_b2, out);

    // 2) h0 = leaky(x_path @ fc1_w^T + b)
    gemm_nt<1><<<dim3(DH / 64, NPATCH / 64), 256>>>(x_path, fc1_w, fc1_b, H, NPATCH, DH, DIN);

    // 3) h = 0.5*(h0 + colmean(h0))
    colsum_partial<<<64, 256>>>(H, PART);
    mean_combine<<<1, 512>>>(PART, MEAN);
    h_update<<<NPATCH * DH / 256, 256>>>(H, MEAN);

    // 4) e_h, e_t
    gemm_nt<0><<<dim3(DH / 64, NPATCH / 64), 256>>>(H, wh_w, wh_b, EH, NPATCH, DH, DH);
    gemm_nt<0><<<dim3(DH / 64, NPATCH / 64), 256>>>(H, wt_w, wt_b, ET, NPATCH, DH, DH);

    // 5) fused logits + top-6 (FFMA2, double-buffered)
    cudaFuncSetAttribute(logits_topk, cudaFuncAttributeMaxDynamicSharedMemorySize, LT_SMEM);
    logits_topk<<<NPATCH / 64, 256, LT_SMEM>>>(EH, ET, TOPV, TOPI);

    // 6) kNN aggregation -> U = e_h + e_Nh, V = e_h * e_Nh
    knn_epi<<<NPATCH, 128>>>(EH, ET, TOPV, TOPI, U, V);

    // 7) e_h2 = leaky(U@l1^T+b1) + leaky(V@l2^T+b2)  -> out
    gemm_nt<1><<<dim3(DH / 64, NPATCH / 64), 256>>>(U, l1w, l1b, out_eh2, NPATCH, DH, DH);
    gemm_nt<2><<<dim3(DH / 64, NPATCH / 64), 256>>>(V, l2w, l2b, out_eh2, NPATCH, DH, DH);

    // 8) attention readout -> e_g
    gemm_nt<1><<<dim3(HSNN / 64, NPATCH / 64), 256>>>(out_eh2, aw1, ab1, G1, NPATCH, HSNN, DH);
    att_score<<<NPATCH / 8, 256>>>(G1, aw2, ab2, GS);
    softmax_n<<<1, 1024>>>(GS, AB);
    eg_partial<<<64, 256>>>(AB, out_eh2, P2);
    eg_combine<<<1, 512>>>(P2, out_eg);
}

// round 12
// speedup vs baseline: 1.7217x; 1.5756x over previous
#include <cuda_runtime.h>
#include <math.h>

#define NPATCH 8192
#define DIN    384
#define DH     512
#define HSNN   256
#define TOPK   6
#define NCAND  16

typedef unsigned long long ull;
typedef unsigned int uint;

__device__ __forceinline__ void ffma2(ull& d, ull a, ull b) {
    asm("fma.rn.f32x2 %0, %1, %2, %0;" : "+l"(d) : "l"(a), "l"(b));
}
__device__ __forceinline__ float psum(ull v) {
    float lo = __uint_as_float((unsigned)(v & 0xffffffffu));
    float hi = __uint_as_float((unsigned)(v >> 32));
    return lo + hi;
}
__device__ __forceinline__ uint f2tf32(float f) {
    uint u;
    asm("cvt.rna.tf32.f32 %0, %1;" : "=r"(u) : "f"(f));
    return u;
}
__device__ __forceinline__ void mma_tf32(float& c0, float& c1, float& c2, float& c3,
                                         uint a0, uint a1, uint a2, uint a3,
                                         uint b0, uint b1) {
    asm("mma.sync.aligned.m16n8k8.row.col.f32.tf32.tf32.f32 "
        "{%0,%1,%2,%3}, {%4,%5,%6,%7}, {%8,%9}, {%0,%1,%2,%3};"
        : "+f"(c0), "+f"(c1), "+f"(c2), "+f"(c3)
        : "r"(a0), "r"(a1), "r"(a2), "r"(a3), "r"(b0), "r"(b1));
}

// ---------------- scratch (static device allocations; no cudaMalloc) --------
__device__ float g_H [NPATCH * DH];
__device__ float g_EH[NPATCH * DH];
__device__ float g_ET[NPATCH * DH];
__device__ float g_U [NPATCH * DH];
__device__ float g_V [NPATCH * DH];
__device__ float g_G1[NPATCH * HSNN];
__device__ float g_PART[64 * DH];
__device__ float g_MEAN[DH];
__device__ float g_GS[NPATCH];
__device__ float g_AB[NPATCH];
__device__ int   g_TOPI[NPATCH * NCAND];
__device__ float g_P2[64 * DH];

// ---------------- omic SNN branches -----------------------------------------
struct OmicArgs {
    const float* x[6];
    const float* w1[6];
    int s[6];
};

__global__ void omic_kernel(OmicArgs oa, const float* __restrict__ sig_b1,
                            const float* __restrict__ sig_w2,
                            const float* __restrict__ sig_b2,
                            float* __restrict__ out) {
    __shared__ float sx[1536];
    __shared__ float h1[HSNN];
    int br = blockIdx.x, tid = threadIdx.x;
    int s = oa.s[br];
    const float* x = oa.x[br];
    for (int j = tid; j < s; j += 256) sx[j] = x[j];
    __syncthreads();
    const float* w = oa.w1[br] + (size_t)tid * s;
    float acc = sig_b1[br * HSNN + tid];
    for (int j = 0; j < s; j++) acc += w[j] * sx[j];
    h1[tid] = acc > 0.f ? acc : expm1f(acc);
    __syncthreads();
    const float* w2 = sig_w2 + (size_t)br * HSNN * HSNN + (size_t)tid * HSNN;
    float acc2 = sig_b2[br * HSNN + tid];
    #pragma unroll 8
    for (int j = 0; j < HSNN; j++) acc2 += w2[j] * h1[j];
    out[br * HSNN + tid] = acc2 > 0.f ? acc2 : expm1f(acc2);
}

// ---------------- packed (FFMA2) NT GEMM (unchanged, passing) ----------------
template <int EPI>
__global__ void gemm_nt(const float* __restrict__ A, const float* __restrict__ B,
                        const float* __restrict__ bias, float* __restrict__ C,
                        int M, int N, int K) {
    __shared__ float As2[8 * 128 + 32];
    __shared__ float Bs2[8 * 128 + 32];
    const int bi = blockIdx.y * 64;
    const int bj = blockIdx.x * 64;
    const int tid = threadIdx.x;
    const int tx = tid & 15;
    const int ty = tid >> 4;
    const int lr = tid >> 2;
    const int lk = (tid & 3) * 4;

    ull acc[4][4] = {};
    for (int k0 = 0; k0 < K; k0 += 16) {
        float4 a4 = *(const float4*)(A + (size_t)(bi + lr) * K + k0 + lk);
        float4 b4 = *(const float4*)(B + (size_t)(bj + lr) * K + k0 + lk);
        __syncthreads();
        int k2a = lk >> 1;
        *(float2*)&As2[k2a * 128 + (k2a & 7) * 4 + lr * 2] = make_float2(a4.x, a4.y);
        *(float2*)&As2[(k2a + 1) * 128 + ((k2a + 1) & 7) * 4 + lr * 2] = make_float2(a4.z, a4.w);
        *(float2*)&Bs2[k2a * 128 + (k2a & 7) * 4 + lr * 2] = make_float2(b4.x, b4.y);
        *(float2*)&Bs2[(k2a + 1) * 128 + ((k2a + 1) & 7) * 4 + lr * 2] = make_float2(b4.z, b4.w);
        __syncthreads();
        #pragma unroll
        for (int k2 = 0; k2 < 8; k2++) {
            const float* ab = As2 + k2 * 128 + (k2 & 7) * 4;
            const float* bb = Bs2 + k2 * 128 + (k2 & 7) * 4 + tx * 2;
            ulonglong2 a01 = *(const ulonglong2*)(ab + ty * 8);
            ulonglong2 a23 = *(const ulonglong2*)(ab + ty * 8 + 4);
            #pragma unroll
            for (int c = 0; c < 4; c++) {
                ull bv = *(const ull*)(bb + c * 32);
                ffma2(acc[0][c], a01.x, bv);
                ffma2(acc[1][c], a01.y, bv);
                ffma2(acc[2][c], a23.x, bv);
                ffma2(acc[3][c], a23.y, bv);
            }
        }
    }
    #pragma unroll
    for (int ii = 0; ii < 4; ii++) {
        int i = bi + ty * 4 + ii;
        #pragma unroll
        for (int c = 0; c < 4; c++) {
            int j = bj + tx + 16 * c;
            float v = psum(acc[ii][c]) + bias[j];
            if (EPI >= 1) v = v >= 0.f ? v : 0.01f * v;
            if (EPI == 2) C[(size_t)i * N + j] += v;
            else          C[(size_t)i * N + j]  = v;
        }
    }
}

// ---------------- column mean of H, then h = 0.5*(h + mean) ------------------
__global__ void colsum_partial(const float* __restrict__ H, float* __restrict__ part) {
    int b = blockIdx.x, tid = threadIdx.x;
    const float* base = H + (size_t)b * 128 * DH;
    float a0 = 0.f, a1 = 0.f;
    for (int r = 0; r < 128; r++) {
        a0 += base[r * DH + tid];
        a1 += base[r * DH + tid + 256];
    }
    part[b * DH + tid] = a0;
    part[b * DH + tid + 256] = a1;
}

__global__ void mean_combine(const float* __restrict__ part, float* __restrict__ mean) {
    int d = threadIdx.x;
    float s = 0.f;
    for (int b = 0; b < 64; b++) s += part[b * DH + d];
    mean[d] = s * (1.f / (float)NPATCH);
}

__global__ void h_update(float* __restrict__ H, const float* __restrict__ mean) {
    int idx = blockIdx.x * 256 + threadIdx.x;
    H[idx] = 0.5f * (H[idx] + mean[idx & (DH - 1)]);
}

// ---------------- fused tf32-MMA logits + per-row top-16 candidates ----------
#define LSTRIDE 129
#define LT_AS   (64 * 512)            // uints
#define LT_BTILE 4096                 // uints per B buffer (128 cols x 32 k)
#define LT_BS   (2 * LT_BTILE)
#define LT_LS   (64 * LSTRIDE)
#define LT_MV   (64 * 4 * NCAND)
#define LT_SMEM ((LT_AS + LT_BS + LT_LS + 2 * LT_MV) * 4)

__device__ __forceinline__ void fill_b_chunk(uint* __restrict__ dst,
                                             const float* __restrict__ ET,
                                             int bj, int k0, int tid) {
    #pragma unroll
    for (int it = 0; it < 8; it++) {
        int s = tid + it * 256;              // 0..2047 float2-units
        int l = s & 31, q = (s >> 5) & 3, nt = s >> 7;
        int n = bj + nt * 8 + (l >> 2);
        int kk = k0 + q * 8 + (l & 3);
        const float* p = ET + (size_t)n * DH + kk;
        uint2 v = make_uint2(f2tf32(p[0]), f2tf32(p[4]));
        *(uint2*)&dst[s * 2] = v;
    }
}

// static-index bubble insertion (no dynamic register indexing)
template <int NC>
__device__ __forceinline__ void topk_insert(float (&lv)[NC], int (&li)[NC],
                                            float v, int ix) {
    if (v > lv[NC - 1]) {
        lv[NC - 1] = v; li[NC - 1] = ix;
        #pragma unroll
        for (int q = NC - 1; q > 0; q--) {
            if (lv[q] > lv[q - 1]) {
                float tf = lv[q]; lv[q] = lv[q - 1]; lv[q - 1] = tf;
                int  t2 = li[q]; li[q] = li[q - 1]; li[q - 1] = t2;
            }
        }
    }
}

__global__ __launch_bounds__(256, 1)
void logits_topk(const float* __restrict__ EH, const float* __restrict__ ET,
                 int* __restrict__ topi) {
    extern __shared__ uint smu[];
    uint*  As = smu;
    uint*  Bs = As + LT_AS;
    float* Ls = (float*)(Bs + LT_BS);
    float* mv = Ls + LT_LS;
    int*   mi = (int*)(mv + LT_MV);
    const int tid = threadIdx.x;
    const int lane = tid & 31;
    const int wid = tid >> 5;
    const int wm = wid >> 2;          // 0..1 (row group of 32)
    const int wn = wid & 3;           // 0..3 (col group of 32)
    const int bi = blockIdx.x * 64;

    // one-time A slab fill in fragment order
    for (int u = tid; u < 64 * 512; u += 256) {
        int t = u >> 13;
        int v = u & 8191;
        int q = v >> 7;
        int w = v & 127;
        int l = w >> 2, r = w & 3;
        int row = t * 16 + (l >> 2) + (r & 1) * 8;
        int col = q * 8 + (l & 3) + (r >> 1) * 4;
        As[u] = f2tf32(EH[(size_t)(bi + row) * DH + col]);
    }

    float tv[NCAND]; int ti[NCAND];
    #pragma unroll
    for (int k = 0; k < NCAND; k++) { tv[k] = -INFINITY; ti[k] = 0; }
    __syncthreads();

    for (int bj = 0; bj < NPATCH; bj += 128) {
        float acc[2][4][4];
        #pragma unroll
        for (int mt = 0; mt < 2; mt++)
            #pragma unroll
            for (int nt = 0; nt < 4; nt++)
                #pragma unroll
                for (int c = 0; c < 4; c++) acc[mt][nt][c] = 0.f;

        fill_b_chunk(Bs, ET, bj, 0, tid);
        __syncthreads();
        for (int ch = 0; ch < 16; ch++) {
            const uint* cur = Bs + (ch & 1) * LT_BTILE;
            if (ch < 15) fill_b_chunk(Bs + ((ch + 1) & 1) * LT_BTILE, ET, bj, (ch + 1) * 32, tid);
            #pragma unroll
            for (int q = 0; q < 4; q++) {
                int Q = ch * 4 + q;
                uint4 af[2];
                #pragma unroll
                for (int mt = 0; mt < 2; mt++)
                    af[mt] = *(const uint4*)&As[((wm * 2 + mt) * 64 + Q) * 128 + lane * 4];
                uint2 bf[4];
                #pragma unroll
                for (int nt = 0; nt < 4; nt++)
                    bf[nt] = *(const uint2*)&cur[((wn * 4 + nt) * 4 + q) * 64 + lane * 2];
                #pragma unroll
                for (int mt = 0; mt < 2; mt++)
                    #pragma unroll
                    for (int nt = 0; nt < 4; nt++)
                        mma_tf32(acc[mt][nt][0], acc[mt][nt][1], acc[mt][nt][2], acc[mt][nt][3],
                                 af[mt].x, af[mt].y, af[mt].z, af[mt].w,
                                 bf[nt].x, bf[nt].y);
            }
            __syncthreads();
        }
        // write logits tile to smem (selection only)
        {
            int g = lane >> 2, c2 = (lane & 3) * 2;
            #pragma unroll
            for (int mt = 0; mt < 2; mt++) {
                int r0 = wm * 32 + mt * 16 + g;
                #pragma unroll
                for (int nt = 0; nt < 4; nt++) {
                    int cb = wn * 32 + nt * 8 + c2;
                    Ls[r0 * LSTRIDE + cb]           = acc[mt][nt][0];
                    Ls[r0 * LSTRIDE + cb + 1]       = acc[mt][nt][1];
                    Ls[(r0 + 8) * LSTRIDE + cb]     = acc[mt][nt][2];
                    Ls[(r0 + 8) * LSTRIDE + cb + 1] = acc[mt][nt][3];
                }
            }
        }
        __syncthreads();
        // parallel local top-16: 4 threads/row, bank-staggered 32-col blocks
        {
            int srow = tid >> 2, q = tid & 3;
            float lv[NCAND]; int li[NCAND];
            #pragma unroll
            for (int k = 0; k < NCAND; k++) { lv[k] = -INFINITY; li[k] = 0; }
            const float* rp = Ls + srow * LSTRIDE + q * 32;
            for (int t = 0; t < 32; t++) {
                int cc = (t + q * 8) & 31;
                topk_insert<NCAND>(lv, li, rp[cc], bj + q * 32 + cc);
            }
            #pragma unroll
            for (int k = 0; k < NCAND; k++) {
                mv[(srow * 4 + q) * NCAND + k] = lv[k];
                mi[(srow * 4 + q) * NCAND + k] = li[k];
            }
        }
        __syncthreads();
        if (tid < 64) {
            for (int s = 0; s < 4 * NCAND; s++)
                topk_insert<NCAND>(tv, ti, mv[tid * 4 * NCAND + s], mi[tid * 4 * NCAND + s]);
        }
    }
    if (tid < 64) {
        #pragma unroll
        for (int k = 0; k < NCAND; k++)
            topi[(size_t)(bi + tid) * NCAND + k] = ti[k];
    }
}

// ---------------- per-row kNN: exact fp32 rescore of 16 cands, top-6, agg ----
__global__ void knn_epi(const float* __restrict__ EH, const float* __restrict__ ET,
                        const int* __restrict__ topi,
                        float* __restrict__ U, float* __restrict__ V) {
    __shared__ float wL[NCAND][4], wN[NCAND][4];
    __shared__ float wG[TOPK][4];
    const int i = blockIdx.x, tid = threadIdx.x;  // 128 threads
    const int lane = tid & 31, w = tid >> 5;
    const float scale = 0.04419417382415922f;  // 512^-0.5

    int idx[NCAND];
    #pragma unroll
    for (int c = 0; c < NCAND; c++) idx[c] = topi[(size_t)i * NCAND + c];

    float eh[4];
    #pragma unroll
    for (int c = 0; c < 4; c++) eh[c] = EH[(size_t)i * DH + tid + 128 * c];

    // exact logit + neighbor sum for each of 16 candidates
    for (int c = 0; c < NCAND; c++) {
        const float* et = ET + (size_t)idx[c] * DH;
        float sL = 0.f, sN = 0.f;
        #pragma unroll
        for (int cc = 0; cc < 4; cc++) {
            float nb = et[tid + 128 * cc];
            sL += eh[cc] * nb;
            sN += nb;
        }
        #pragma unroll
        for (int off = 16; off; off >>= 1) {
            sL += __shfl_down_sync(0xffffffffu, sL, off);
            sN += __shfl_down_sync(0xffffffffu, sN, off);
        }
        if (lane == 0) { wL[c][w] = sL; wN[c][w] = sN; }
    }
    __syncthreads();

    float cval[NCAND];
    #pragma unroll
    for (int c = 0; c < NCAND; c++)
        cval[c] = (wL[c][0] + wL[c][1] + wL[c][2] + wL[c][3]) * scale;

    // exact top-6 among 16 (value desc, lower patch-index on ties) —
    // computed identically (deterministically) by all threads
    int selc[TOPK];
    unsigned used = 0;
    #pragma unroll
    for (int k = 0; k < TOPK; k++) {
        float best = -INFINITY; int bc = -1, bix = 0x7fffffff;
        #pragma unroll
        for (int c = 0; c < NCAND; c++) {
            if (!(used & (1u << c))) {
                float v = cval[c];
                if (v > best || (v == best && idx[c] < bix)) { best = v; bc = c; bix = idx[c]; }
            }
        }
        selc[k] = bc;
        used |= 1u << bc;
    }

    float vals[TOPK], sN6[TOPK];
    int sidx[TOPK];
    #pragma unroll
    for (int k = 0; k < TOPK; k++) {
        int c = selc[k];
        vals[k] = cval[c];
        sN6[k] = wN[c][0] + wN[c][1] + wN[c][2] + wN[c][3];
        sidx[k] = idx[c];
    }

    float m = vals[0];
    #pragma unroll
    for (int k = 1; k < TOPK; k++) m = fmaxf(m, vals[k]);
    float se = 0.f, p[TOPK];
    #pragma unroll
    for (int k = 0; k < TOPK; k++) { p[k] = expf(vals[k] - m); se += p[k]; }
    float inv = 1.f / se;
    #pragma unroll
    for (int k = 0; k < TOPK; k++) p[k] *= inv;

    // gate sums for the 6 selected (reload their et rows; L2-hot)
    float Nb[TOPK][4];
    for (int k = 0; k < TOPK; k++) {
        const float* et = ET + (size_t)sidx[k] * DH;
        float sG = 0.f;
        #pragma unroll
        for (int cc = 0; cc < 4; cc++) {
            float nb = et[tid + 128 * cc];
            Nb[k][cc] = nb;
            float ehr = p[k] * nb + (1.f - p[k]) * eh[cc];
            sG += tanhf(eh[cc] + ehr);
        }
        #pragma unroll
        for (int off = 16; off; off >>= 1)
            sG += __shfl_down_sync(0xffffffffu, sG, off);
        if (lane == 0) wG[k][w] = sG;
    }
    __syncthreads();

    float ka[TOPK], kp[TOPK];
    #pragma unroll
    for (int k = 0; k < TOPK; k++)
        ka[k] = sN6[k] * (wG[k][0] + wG[k][1] + wG[k][2] + wG[k][3]);
    m = ka[0];
    #pragma unroll
    for (int k = 1; k < TOPK; k++) m = fmaxf(m, ka[k]);
    se = 0.f;
    #pragma unroll
    for (int k = 0; k < TOPK; k++) { kp[k] = expf(ka[k] - m); se += kp[k]; }
    inv = 1.f / se;
    float enh[4] = {0.f, 0.f, 0.f, 0.f};
    #pragma unroll
    for (int k = 0; k < TOPK; k++)
        #pragma unroll
        for (int cc = 0; cc < 4; cc++) enh[cc] += kp[k] * inv * Nb[k][cc];
    #pragma unroll
    for (int cc = 0; cc < 4; cc++) {
        size_t o = (size_t)i * DH + tid + 128 * cc;
        U[o] = eh[cc] + enh[cc];
        V[o] = eh[cc] * enh[cc];
    }
}

// ---------------- attention readout ------------------------------------------
__global__ void att_score(const float* __restrict__ G1, const float* __restrict__ aw2,
                          const float* __restrict__ ab2, float* __restrict__ Gs) {
    int warp = threadIdx.x >> 5, lane = threadIdx.x & 31;
    int row = blockIdx.x * 8 + warp;
    float s = 0.f;
    #pragma unroll
    for (int c = 0; c < 8; c++) {
        int j = lane + 32 * c;
        s += G1[(size_t)row * HSNN + j] * aw2[j];
    }
    #pragma unroll
    for (int off = 16; off; off >>= 1) s += __shfl_down_sync(0xffffffffu, s, off);
    if (lane == 0) Gs[row] = s + ab2[0];
}

__global__ void softmax_n(const float* __restrict__ Gs, float* __restrict__ A) {
    __shared__ float sm[32];
    int tid = threadIdx.x;  // 1024
    int lane = tid & 31, warp = tid >> 5;
    float v[8], m = -INFINITY;
    #pragma unroll
    for (int c = 0; c < 8; c++) { v[c] = Gs[tid + 1024 * c]; m = fmaxf(m, v[c]); }
    #pragma unroll
    for (int off = 16; off; off >>= 1) m = fmaxf(m, __shfl_xor_sync(0xffffffffu, m, off));
    if (lane == 0) sm[warp] = m;
    __syncthreads();
    if (tid < 32) {
        float t = sm[tid];
        #pragma unroll
        for (int off = 16; off; off >>= 1) t = fmaxf(t, __shfl_xor_sync(0xffffffffu, t, off));
        if (tid == 0) sm[0] = t;
    }
    __syncthreads();
    m = sm[0];
    __syncthreads();
    float e[8], s = 0.f;
    #pragma unroll
    for (int c = 0; c < 8; c++) { e[c] = expf(v[c] - m); s += e[c]; }
    #pragma unroll
    for (int off = 16; off; off >>= 1) s += __shfl_xor_sync(0xffffffffu, s, off);
    if (lane == 0) sm[warp] = s;
    __syncthreads();
    if (tid < 32) {
        float t = sm[tid];
        #pragma unroll
        for (int off = 16; off; off >>= 1) t += __shfl_xor_sync(0xffffffffu, t, off);
        if (tid == 0) sm[0] = t;
    }
    __syncthreads();
    float inv = 1.f / sm[0];
    #pragma unroll
    for (int c = 0; c < 8; c++) A[tid + 1024 * c] = e[c] * inv;
}

__global__ void eg_partial(const float* __restrict__ A, const float* __restrict__ X,
                           float* __restrict__ P2) {
    int b = blockIdx.x, tid = threadIdx.x;
    float a0 = 0.f, a1 = 0.f;
    for (int r = 0; r < 128; r++) {
        int n = b * 128 + r;
        float a = A[n];
        a0 += a * X[(size_t)n * DH + tid];
        a1 += a * X[(size_t)n * DH + tid + 256];
    }
    P2[b * DH + tid] = a0;
    P2[b * DH + tid + 256] = a1;
}

__global__ void eg_combine(const float* __restrict__ P2, float* __restrict__ eg) {
    int d = threadIdx.x;
    float s = 0.f;
    for (int b = 0; b < 64; b++) s += P2[b * DH + d];
    eg[d] = s;
}

// ---------------- host ------------------------------------------------------
extern "C" void kernel_launch(void* const* d_in, const int* in_sizes, int n_in,
                              void* d_out, int out_size) {
    const float *xo[6], *w1[6];
    int s6[6];
    const float *x_path, *sig_b1, *sig_w2, *sig_b2;

    bool dictOrder = (in_sizes[12] == NPATCH * DIN);
    if (dictOrder) {
        for (int i = 0; i < 6; i++) {
            xo[i] = (const float*)d_in[2 * i];
            w1[i] = (const float*)d_in[2 * i + 1];
            s6[i] = in_sizes[2 * i];
        }
        x_path = (const float*)d_in[12];
        sig_b1 = (const float*)d_in[13];
        sig_w2 = (const float*)d_in[14];
        sig_b2 = (const float*)d_in[15];
    } else {
        for (int i = 0; i < 6; i++) {
            xo[i] = (const float*)d_in[i];
            w1[i] = (const float*)d_in[6 + i];
            s6[i] = in_sizes[i];
        }
        sig_b1 = (const float*)d_in[12];
        sig_w2 = (const float*)d_in[13];
        sig_b2 = (const float*)d_in[14];
        x_path = (const float*)d_in[15];
    }
    const float* fc1_w = (const float*)d_in[16];
    const float* fc1_b = (const float*)d_in[17];
    const float* wh_w  = (const float*)d_in[18];
    const float* wh_b  = (const float*)d_in[19];
    const float* wt_w  = (const float*)d_in[20];
    const float* wt_b  = (const float*)d_in[21];
    const float* l1w   = (const float*)d_in[22];
    const float* l1b   = (const float*)d_in[23];
    const float* l2w   = (const float*)d_in[24];
    const float* l2b   = (const float*)d_in[25];
    const float* aw1   = (const float*)d_in[26];
    const float* ab1   = (const float*)d_in[27];
    const float* aw2   = (const float*)d_in[28];
    const float* ab2   = (const float*)d_in[29];

    float* out     = (float*)d_out;
    float* out_eh2 = out + 6 * HSNN;
    float* out_eg  = out + 6 * HSNN + NPATCH * DH;

    float *H, *EH, *ET, *U, *V, *G1, *PART, *MEAN, *GS, *AB, *P2;
    int* TOPI;
    cudaGetSymbolAddress((void**)&H,    g_H);
    cudaGetSymbolAddress((void**)&EH,   g_EH);
    cudaGetSymbolAddress((void**)&ET,   g_ET);
    cudaGetSymbolAddress((void**)&U,    g_U);
    cudaGetSymbolAddress((void**)&V,    g_V);
    cudaGetSymbolAddress((void**)&G1,   g_G1);
    cudaGetSymbolAddress((void**)&PART, g_PART);
    cudaGetSymbolAddress((void**)&MEAN, g_MEAN);
    cudaGetSymbolAddress((void**)&GS,   g_GS);
    cudaGetSymbolAddress((void**)&AB,   g_AB);
    cudaGetSymbolAddress((void**)&TOPI, g_TOPI);
    cudaGetSymbolAddress((void**)&P2,   g_P2);

    OmicArgs oa;
    for (int i = 0; i < 6; i++) { oa.x[i] = xo[i]; oa.w1[i] = w1[i]; oa.s[i] = s6[i]; }

    // 1) omic branches -> out[0:1536]
    omic_kernel<<<6, 256>>>(oa, sig_b1, sig_w2, sig_b2, out);

    // 2) h0 = leaky(x_path @ fc1_w^T + b)
    gemm_nt<1><<<dim3(DH / 64, NPATCH / 64), 256>>>(x_path, fc1_w, fc1_b, H, NPATCH, DH, DIN);

    // 3) h = 0.5*(h0 + colmean(h0))
    colsum_partial<<<64, 256>>>(H, PART);
    mean_combine<<<1, 512>>>(PART, MEAN);
    h_update<<<NPATCH * DH / 256, 256>>>(H, MEAN);

    // 4) e_h, e_t
    gemm_nt<0><<<dim3(DH / 64, NPATCH / 64), 256>>>(H, wh_w, wh_b, EH, NPATCH, DH, DH);
    gemm_nt<0><<<dim3(DH / 64, NPATCH / 64), 256>>>(H, wt_w, wt_b, ET, NPATCH, DH, DH);

    // 5) fused tf32-MMA logits + top-16 candidates
    cudaFuncSetAttribute(logits_topk, cudaFuncAttributeMaxDynamicSharedMemorySize, LT_SMEM);
    logits_topk<<<NPATCH / 64, 256, LT_SMEM>>>(EH, ET, TOPI);

    // 6) exact rescore + top-6 + kNN aggregation -> U, V
    knn_epi<<<NPATCH, 128>>>(EH, ET, TOPI, U, V);

    // 7) e_h2 = leaky(U@l1^T+b1) + leaky(V@l2^T+b2)  -> out
    gemm_nt<1><<<dim3(DH / 64, NPATCH / 64), 256>>>(U, l1w, l1b, out_eh2, NPATCH, DH, DH);
    gemm_nt<2><<<dim3(DH / 64, NPATCH / 64), 256>>>(V, l2w, l2b, out_eh2, NPATCH, DH, DH);

    // 8) attention readout -> e_g
    gemm_nt<1><<<dim3(HSNN / 64, NPATCH / 64), 256>>>(out_eh2, aw1, ab1, G1, NPATCH, HSNN, DH);
    att_score<<<NPATCH / 8, 256>>>(G1, aw2, ab2, GS);
    softmax_n<<<1, 1024>>>(GS, AB);
    eg_partial<<<64, 256>>>(AB, out_eh2, P2);
    eg_combine<<<1, 512>>>(P2, out_eg);
}

// round 14
// speedup vs baseline: 1.7223x; 1.0004x over previous
#include <cuda_runtime.h>
#include <math.h>

#define NPATCH 8192
#define DIN    384
#define DH     512
#define HSNN   256
#define TOPK   6
#define NCAND  16

typedef unsigned int uint;

__device__ __forceinline__ uint f2tf32(float f) {
    uint u;
    asm("cvt.rna.tf32.f32 %0, %1;" : "=r"(u) : "f"(f));
    return u;
}
__device__ __forceinline__ void mma_tf32(float& c0, float& c1, float& c2, float& c3,
                                         uint a0, uint a1, uint a2, uint a3,
                                         uint b0, uint b1) {
    asm("mma.sync.aligned.m16n8k8.row.col.f32.tf32.tf32.f32 "
        "{%0,%1,%2,%3}, {%4,%5,%6,%7}, {%8,%9}, {%0,%1,%2,%3};"
        : "+f"(c0), "+f"(c1), "+f"(c2), "+f"(c3)
        : "r"(a0), "r"(a1), "r"(a2), "r"(a3), "r"(b0), "r"(b1));
}

// ---------------- scratch (static device allocations; no cudaMalloc) --------
__device__ float g_H [NPATCH * DH];
__device__ float g_EH[NPATCH * DH];
__device__ float g_ET[NPATCH * DH];
__device__ float g_U [NPATCH * DH];
__device__ float g_V [NPATCH * DH];
__device__ float g_G1[NPATCH * HSNN];
__device__ float g_PART[64 * DH];
__device__ float g_MEAN[DH];
__device__ float g_GS[NPATCH];
__device__ float g_AB[NPATCH];
__device__ int   g_TOPI[NPATCH * NCAND];
__device__ float g_P2[64 * DH];

// ---------------- omic SNN branches -----------------------------------------
struct OmicArgs {
    const float* x[6];
    const float* w1[6];
    int s[6];
};

__global__ void omic_kernel(OmicArgs oa, const float* __restrict__ sig_b1,
                            const float* __restrict__ sig_w2,
                            const float* __restrict__ sig_b2,
                            float* __restrict__ out) {
    __shared__ float sx[1536];
    __shared__ float h1[HSNN];
    int br = blockIdx.x, tid = threadIdx.x;
    int s = oa.s[br];
    const float* x = oa.x[br];
    for (int j = tid; j < s; j += 256) sx[j] = x[j];
    __syncthreads();
    const float* w = oa.w1[br] + (size_t)tid * s;
    float acc = sig_b1[br * HSNN + tid];
    for (int j = 0; j < s; j++) acc += w[j] * sx[j];
    h1[tid] = acc > 0.f ? acc : expm1f(acc);
    __syncthreads();
    const float* w2 = sig_w2 + (size_t)br * HSNN * HSNN + (size_t)tid * HSNN;
    float acc2 = sig_b2[br * HSNN + tid];
    #pragma unroll 8
    for (int j = 0; j < HSNN; j++) acc2 += w2[j] * h1[j];
    out[br * HSNN + tid] = acc2 > 0.f ? acc2 : expm1f(acc2);
}

// ---------------- 3xTF32 tensor-core NT GEMM ---------------------------------
// C[i,j] = sum_k A[i,k]*B[j,k] + bias[j], fp32-equivalent via hi/lo split.
// CTA tile 128x64, 256 thr = 8 warps (4M x 2N), warp tile 32x32 (m16n8k8).
// K-chunks of 32, double-buffered; hi/lo fragment-order smem.
// EPI: 0 = store(bias), 1 = store(leaky(bias+)), 2 = C += leaky(bias+)
#define GT_AH  0
#define GT_AL  4096
#define GT_BH  8192
#define GT_BL  10240
#define GT_BUF 12288
#define GT_SMEM (2 * GT_BUF * 4)   // 98304 bytes

__device__ __forceinline__ void gt_fill(uint* __restrict__ sm,
                                        const float* __restrict__ A,
                                        const float* __restrict__ B,
                                        int bi, int bj, int k0, int K, int tid) {
    // A: 128 rows x 32 k, fragment order (t=0..7 m-frags, q=0..3, lane, r=0..3)
    #pragma unroll
    for (int it = 0; it < 4; it++) {
        int s = tid + it * 256;            // 0..1023
        int t = s >> 7, q = (s >> 5) & 3, l = s & 31;
        const float* pa = A + (size_t)(bi + t * 16 + (l >> 2)) * K + k0 + q * 8 + (l & 3);
        float a00 = pa[0], a01 = pa[4];
        float a10 = pa[8 * (size_t)K], a11 = pa[8 * (size_t)K + 4];
        uint h00 = f2tf32(a00), h01 = f2tf32(a01), h10 = f2tf32(a10), h11 = f2tf32(a11);
        float l00 = a00 - __uint_as_float(h00);
        float l01 = a01 - __uint_as_float(h01);
        float l10 = a10 - __uint_as_float(h10);
        float l11 = a11 - __uint_as_float(h11);
        int base = ((t * 4 + q) * 32 + l) * 4;
        *(uint4*)&sm[GT_AH + base] = make_uint4(h00, h10, h01, h11);
        *(uint4*)&sm[GT_AL + base] = make_uint4(f2tf32(l00), f2tf32(l10), f2tf32(l01), f2tf32(l11));
    }
    // B: 64 rows x 32 k, fragment order (nt=0..7 n-frags, q, lane, r=0..1)
    #pragma unroll
    for (int it = 0; it < 4; it++) {
        int s = tid + it * 256;            // 0..1023
        int nt = s >> 7, q = (s >> 5) & 3, l = s & 31;
        const float* pb = B + (size_t)(bj + nt * 8 + (l >> 2)) * K + k0 + q * 8 + (l & 3);
        float b0 = pb[0], b1 = pb[4];
        uint h0 = f2tf32(b0), h1 = f2tf32(b1);
        float lo0 = b0 - __uint_as_float(h0);
        float lo1 = b1 - __uint_as_float(h1);
        int base = ((nt * 4 + q) * 32 + l) * 2;
        *(uint2*)&sm[GT_BH + base] = make_uint2(h0, h1);
        *(uint2*)&sm[GT_BL + base] = make_uint2(f2tf32(lo0), f2tf32(lo1));
    }
}

template <int EPI>
__global__ __launch_bounds__(256, 2)
void gemm_tf32(const float* __restrict__ A, const float* __restrict__ B,
               const float* __restrict__ bias, float* __restrict__ C,
               int M, int N, int K) {
    extern __shared__ uint gsm[];
    const int tid = threadIdx.x, lane = tid & 31, wid = tid >> 5;
    const int wm = wid >> 1, wn = wid & 1;
    const int bi = blockIdx.y * 128, bj = blockIdx.x * 64;
    const int nk = K / 32;

    float acc[2][4][4] = {};

    gt_fill(gsm, A, B, bi, bj, 0, K, tid);
    __syncthreads();
    for (int ch = 0; ch < nk; ch++) {
        const uint* cur = gsm + (ch & 1) * GT_BUF;
        if (ch + 1 < nk)
            gt_fill(gsm + ((ch + 1) & 1) * GT_BUF, A, B, bi, bj, (ch + 1) * 32, K, tid);
        #pragma unroll
        for (int q = 0; q < 4; q++) {
            uint4 ah[2], al[2];
            uint2 bh[4], bl[4];
            #pragma unroll
            for (int mt = 0; mt < 2; mt++) {
                int base = (((wm * 2 + mt) * 4 + q) * 32 + lane) * 4;
                ah[mt] = *(const uint4*)&cur[GT_AH + base];
                al[mt] = *(const uint4*)&cur[GT_AL + base];
            }
            #pragma unroll
            for (int nt = 0; nt < 4; nt++) {
                int base = (((wn * 4 + nt) * 4 + q) * 32 + lane) * 2;
                bh[nt] = *(const uint2*)&cur[GT_BH + base];
                bl[nt] = *(const uint2*)&cur[GT_BL + base];
            }
            #pragma unroll
            for (int mt = 0; mt < 2; mt++)
                #pragma unroll
                for (int nt = 0; nt < 4; nt++) {
                    float* c = acc[mt][nt];
                    mma_tf32(c[0], c[1], c[2], c[3],
                             ah[mt].x, ah[mt].y, ah[mt].z, ah[mt].w,
                             bh[nt].x, bh[nt].y);
                    mma_tf32(c[0], c[1], c[2], c[3],
                             ah[mt].x, ah[mt].y, ah[mt].z, ah[mt].w,
                             bl[nt].x, bl[nt].y);
                    mma_tf32(c[0], c[1], c[2], c[3],
                             al[mt].x, al[mt].y, al[mt].z, al[mt].w,
                             bh[nt].x, bh[nt].y);
                }
        }
        __syncthreads();
    }

    // epilogue
    #pragma unroll
    for (int mt = 0; mt < 2; mt++) {
        int i0 = bi + wm * 32 + mt * 16 + (lane >> 2);
        #pragma unroll
        for (int nt = 0; nt < 4; nt++) {
            int j0 = bj + wn * 32 + nt * 8 + 2 * (lane & 3);
            float2 bp = *(const float2*)&bias[j0];
            float v0 = acc[mt][nt][0] + bp.x;
            float v1 = acc[mt][nt][1] + bp.y;
            float v2 = acc[mt][nt][2] + bp.x;
            float v3 = acc[mt][nt][3] + bp.y;
            if (EPI >= 1) {
                v0 = v0 >= 0.f ? v0 : 0.01f * v0;
                v1 = v1 >= 0.f ? v1 : 0.01f * v1;
                v2 = v2 >= 0.f ? v2 : 0.01f * v2;
                v3 = v3 >= 0.f ? v3 : 0.01f * v3;
            }
            float* p0 = &C[(size_t)i0 * N + j0];
            float* p1 = &C[(size_t)(i0 + 8) * N + j0];
            if (EPI == 2) {
                float2 o0 = *(float2*)p0, o1 = *(float2*)p1;
                *(float2*)p0 = make_float2(o0.x + v0, o0.y + v1);
                *(float2*)p1 = make_float2(o1.x + v2, o1.y + v3);
            } else {
                *(float2*)p0 = make_float2(v0, v1);
                *(float2*)p1 = make_float2(v2, v3);
            }
        }
    }
}

// ---------------- column mean of H, then h = 0.5*(h + mean) ------------------
__global__ void colsum_partial(const float* __restrict__ H, float* __restrict__ part) {
    int b = blockIdx.x, tid = threadIdx.x;
    const float* base = H + (size_t)b * 128 * DH;
    float a0 = 0.f, a1 = 0.f;
    for (int r = 0; r < 128; r++) {
        a0 += base[r * DH + tid];
        a1 += base[r * DH + tid + 256];
    }
    part[b * DH + tid] = a0;
    part[b * DH + tid + 256] = a1;
}

__global__ void mean_combine(const float* __restrict__ part, float* __restrict__ mean) {
    int d = threadIdx.x;
    float s = 0.f;
    for (int b = 0; b < 64; b++) s += part[b * DH + d];
    mean[d] = s * (1.f / (float)NPATCH);
}

__global__ void h_update(float* __restrict__ H, const float* __restrict__ mean) {
    int idx = blockIdx.x * 256 + threadIdx.x;
    H[idx] = 0.5f * (H[idx] + mean[idx & (DH - 1)]);
}

// ---------------- fused tf32-MMA logits + per-row top-16 candidates ----------
#define LSTRIDE 129
#define LT_AS   (64 * 512)            // uints
#define LT_BTILE 4096                 // uints per B buffer (128 cols x 32 k)
#define LT_BS   (2 * LT_BTILE)
#define LT_LS   (64 * LSTRIDE)
#define LT_MV   (64 * 4 * NCAND)
#define LT_SMEM ((LT_AS + LT_BS + LT_LS + 2 * LT_MV) * 4)

__device__ __forceinline__ void fill_b_chunk(uint* __restrict__ dst,
                                             const float* __restrict__ ET,
                                             int bj, int k0, int tid) {
    #pragma unroll
    for (int it = 0; it < 8; it++) {
        int s = tid + it * 256;              // 0..2047 float2-units
        int l = s & 31, q = (s >> 5) & 3, nt = s >> 7;
        int n = bj + nt * 8 + (l >> 2);
        int kk = k0 + q * 8 + (l & 3);
        const float* p = ET + (size_t)n * DH + kk;
        uint2 v = make_uint2(f2tf32(p[0]), f2tf32(p[4]));
        *(uint2*)&dst[s * 2] = v;
    }
}

// static-index bubble insertion (no dynamic register indexing)
template <int NC>
__device__ __forceinline__ void topk_insert(float (&lv)[NC], int (&li)[NC],
                                            float v, int ix) {
    if (v > lv[NC - 1]) {
        lv[NC - 1] = v; li[NC - 1] = ix;
        #pragma unroll
        for (int q = NC - 1; q > 0; q--) {
            if (lv[q] > lv[q - 1]) {
                float tf = lv[q]; lv[q] = lv[q - 1]; lv[q - 1] = tf;
                int  t2 = li[q]; li[q] = li[q - 1]; li[q - 1] = t2;
            }
        }
    }
}

__global__ __launch_bounds__(256, 1)
void logits_topk(const float* __restrict__ EH, const float* __restrict__ ET,
                 int* __restrict__ topi) {
    extern __shared__ uint smu[];
    uint*  As = smu;
    uint*  Bs = As + LT_AS;
    float* Ls = (float*)(Bs + LT_BS);
    float* mv = Ls + LT_LS;
    int*   mi = (int*)(mv + LT_MV);
    const int tid = threadIdx.x;
    const int lane = tid & 31;
    const int wid = tid >> 5;
    const int wm = wid >> 2;          // 0..1 (row group of 32)
    const int wn = wid & 3;           // 0..3 (col group of 32)
    const int bi = blockIdx.x * 64;

    // one-time A slab fill in fragment order
    for (int u = tid; u < 64 * 512; u += 256) {
        int t = u >> 13;
        int v = u & 8191;
        int q = v >> 7;
        int w = v & 127;
        int l = w >> 2, r = w & 3;
        int row = t * 16 + (l >> 2) + (r & 1) * 8;
        int col = q * 8 + (l & 3) + (r >> 1) * 4;
        As[u] = f2tf32(EH[(size_t)(bi + row) * DH + col]);
    }

    float tv[NCAND]; int ti[NCAND];
    #pragma unroll
    for (int k = 0; k < NCAND; k++) { tv[k] = -INFINITY; ti[k] = 0; }
    __syncthreads();

    for (int bj = 0; bj < NPATCH; bj += 128) {
        float acc[2][4][4];
        #pragma unroll
        for (int mt = 0; mt < 2; mt++)
            #pragma unroll
            for (int nt = 0; nt < 4; nt++)
                #pragma unroll
                for (int c = 0; c < 4; c++) acc[mt][nt][c] = 0.f;

        fill_b_chunk(Bs, ET, bj, 0, tid);
        __syncthreads();
        for (int ch = 0; ch < 16; ch++) {
            const uint* cur = Bs + (ch & 1) * LT_BTILE;
            if (ch < 15) fill_b_chunk(Bs + ((ch + 1) & 1) * LT_BTILE, ET, bj, (ch + 1) * 32, tid);
            #pragma unroll
            for (int q = 0; q < 4; q++) {
                int Q = ch * 4 + q;
                uint4 af[2];
                #pragma unroll
                for (int mt = 0; mt < 2; mt++)
                    af[mt] = *(const uint4*)&As[((wm * 2 + mt) * 64 + Q) * 128 + lane * 4];
                uint2 bf[4];
                #pragma unroll
                for (int nt = 0; nt < 4; nt++)
                    bf[nt] = *(const uint2*)&cur[((wn * 4 + nt) * 4 + q) * 64 + lane * 2];
                #pragma unroll
                for (int mt = 0; mt < 2; mt++)
                    #pragma unroll
                    for (int nt = 0; nt < 4; nt++)
                        mma_tf32(acc[mt][nt][0], acc[mt][nt][1], acc[mt][nt][2], acc[mt][nt][3],
                                 af[mt].x, af[mt].y, af[mt].z, af[mt].w,
                                 bf[nt].x, bf[nt].y);
            }
            __syncthreads();
        }
        // write logits tile to smem (selection only)
        {
            int g = lane >> 2, c2 = (lane & 3) * 2;
            #pragma unroll
            for (int mt = 0; mt < 2; mt++) {
                int r0 = wm * 32 + mt * 16 + g;
                #pragma unroll
                for (int nt = 0; nt < 4; nt++) {
                    int cb = wn * 32 + nt * 8 + c2;
                    Ls[r0 * LSTRIDE + cb]           = acc[mt][nt][0];
                    Ls[r0 * LSTRIDE + cb + 1]       = acc[mt][nt][1];
                    Ls[(r0 + 8) * LSTRIDE + cb]     = acc[mt][nt][2];
                    Ls[(r0 + 8) * LSTRIDE + cb + 1] = acc[mt][nt][3];
                }
            }
        }
        __syncthreads();
        // parallel local top-16: 4 threads/row, bank-staggered 32-col blocks
        {
            int srow = tid >> 2, q = tid & 3;
            float lv[NCAND]; int li[NCAND];
            #pragma unroll
            for (int k = 0; k < NCAND; k++) { lv[k] = -INFINITY; li[k] = 0; }
            const float* rp = Ls + srow * LSTRIDE + q * 32;
            for (int t = 0; t < 32; t++) {
                int cc = (t + q * 8) & 31;
                topk_insert<NCAND>(lv, li, rp[cc], bj + q * 32 + cc);
            }
            #pragma unroll
            for (int k = 0; k < NCAND; k++) {
                mv[(srow * 4 + q) * NCAND + k] = lv[k];
                mi[(srow * 4 + q) * NCAND + k] = li[k];
            }
        }
        __syncthreads();
        if (tid < 64) {
            for (int s = 0; s < 4 * NCAND; s++)
                topk_insert<NCAND>(tv, ti, mv[tid * 4 * NCAND + s], mi[tid * 4 * NCAND + s]);
        }
    }
    if (tid < 64) {
        #pragma unroll
        for (int k = 0; k < NCAND; k++)
            topi[(size_t)(bi + tid) * NCAND + k] = ti[k];
    }
}

// ---------------- per-row kNN: exact fp32 rescore of 16 cands, top-6, agg ----
__global__ void knn_epi(const float* __restrict__ EH, const float* __restrict__ ET,
                        const int* __restrict__ topi,
                        float* __restrict__ U, float* __restrict__ V) {
    __shared__ float wL[NCAND][4], wN[NCAND][4];
    __shared__ float wG[TOPK][4];
    const int i = blockIdx.x, tid = threadIdx.x;  // 128 threads
    const int lane = tid & 31, w = tid >> 5;
    const float scale = 0.04419417382415922f;  // 512^-0.5

    int idx[NCAND];
    #pragma unroll
    for (int c = 0; c < NCAND; c++) idx[c] = topi[(size_t)i * NCAND + c];

    float eh[4];
    #pragma unroll
    for (int c = 0; c < 4; c++) eh[c] = EH[(size_t)i * DH + tid + 128 * c];

    // exact logit + neighbor sum for each of 16 candidates
    for (int c = 0; c < NCAND; c++) {
        const float* et = ET + (size_t)idx[c] * DH;
        float sL = 0.f, sN = 0.f;
        #pragma unroll
        for (int cc = 0; cc < 4; cc++) {
            float nb = et[tid + 128 * cc];
            sL += eh[cc] * nb;
            sN += nb;
        }
        #pragma unroll
        for (int off = 16; off; off >>= 1) {
            sL += __shfl_down_sync(0xffffffffu, sL, off);
            sN += __shfl_down_sync(0xffffffffu, sN, off);
        }
        if (lane == 0) { wL[c][w] = sL; wN[c][w] = sN; }
    }
    __syncthreads();

    float cval[NCAND];
    #pragma unroll
    for (int c = 0; c < NCAND; c++)
        cval[c] = (wL[c][0] + wL[c][1] + wL[c][2] + wL[c][3]) * scale;

    // exact top-6 among 16 (value desc, lower patch-index on ties) —
    // computed identically (deterministically) by all threads
    int selc[TOPK];
    unsigned used = 0;
    #pragma unroll
    for (int k = 0; k < TOPK; k++) {
        float best = -INFINITY; int bc = -1, bix = 0x7fffffff;
        #pragma unroll
        for (int c = 0; c < NCAND; c++) {
            if (!(used & (1u << c))) {
                float v = cval[c];
                if (v > best || (v == best && idx[c] < bix)) { best = v; bc = c; bix = idx[c]; }
            }
        }
        selc[k] = bc;
        used |= 1u << bc;
    }

    float vals[TOPK], sN6[TOPK];
    int sidx[TOPK];
    #pragma unroll
    for (int k = 0; k < TOPK; k++) {
        int c = selc[k];
        vals[k] = cval[c];
        sN6[k] = wN[c][0] + wN[c][1] + wN[c][2] + wN[c][3];
        sidx[k] = idx[c];
    }

    float m = vals[0];
    #pragma unroll
    for (int k = 1; k < TOPK; k++) m = fmaxf(m, vals[k]);
    float se = 0.f, p[TOPK];
    #pragma unroll
    for (int k = 0; k < TOPK; k++) { p[k] = expf(vals[k] - m); se += p[k]; }
    float inv = 1.f / se;
    #pragma unroll
    for (int k = 0; k < TOPK; k++) p[k] *= inv;

    // gate sums for the 6 selected (reload their et rows; L2-hot)
    float Nb[TOPK][4];
    for (int k = 0; k < TOPK; k++) {
        const float* et = ET + (size_t)sidx[k] * DH;
        float sG = 0.f;
        #pragma unroll
        for (int cc = 0; cc < 4; cc++) {
            float nb = et[tid + 128 * cc];
            Nb[k][cc] = nb;
            float ehr = p[k] * nb + (1.f - p[k]) * eh[cc];
            sG += tanhf(eh[cc] + ehr);
        }
        #pragma unroll
        for (int off = 16; off; off >>= 1)
            sG += __shfl_down_sync(0xffffffffu, sG, off);
        if (lane == 0) wG[k][w] = sG;
    }
    __syncthreads();

    float ka[TOPK], kp[TOPK];
    #pragma unroll
    for (int k = 0; k < TOPK; k++)
        ka[k] = sN6[k] * (wG[k][0] + wG[k][1] + wG[k][2] + wG[k][3]);
    m = ka[0];
    #pragma unroll
    for (int k = 1; k < TOPK; k++) m = fmaxf(m, ka[k]);
    se = 0.f;
    #pragma unroll
    for (int k = 0; k < TOPK; k++) { kp[k] = expf(ka[k] - m); se += kp[k]; }
    inv = 1.f / se;
    float enh[4] = {0.f, 0.f, 0.f, 0.f};
    #pragma unroll
    for (int k = 0; k < TOPK; k++)
        #pragma unroll
        for (int cc = 0; cc < 4; cc++) enh[cc] += kp[k] * inv * Nb[k][cc];
    #pragma unroll
    for (int cc = 0; cc < 4; cc++) {
        size_t o = (size_t)i * DH + tid + 128 * cc;
        U[o] = eh[cc] + enh[cc];
        V[o] = eh[cc] * enh[cc];
    }
}

// ---------------- attention readout ------------------------------------------
__global__ void att_score(const float* __restrict__ G1, const float* __restrict__ aw2,
                          const float* __restrict__ ab2, float* __restrict__ Gs) {
    int warp = threadIdx.x >> 5, lane = threadIdx.x & 31;
    int row = blockIdx.x * 8 + warp;
    float s = 0.f;
    #pragma unroll
    for (int c = 0; c < 8; c++) {
        int j = lane + 32 * c;
        s += G1[(size_t)row * HSNN + j] * aw2[j];
    }
    #pragma unroll
    for (int off = 16; off; off >>= 1) s += __shfl_down_sync(0xffffffffu, s, off);
    if (lane == 0) Gs[row] = s + ab2[0];
}

__global__ void softmax_n(const float* __restrict__ Gs, float* __restrict__ A) {
    __shared__ float sm[32];
    int tid = threadIdx.x;  // 1024
    int lane = tid & 31, warp = tid >> 5;
    float v[8], m = -INFINITY;
    #pragma unroll
    for (int c = 0; c < 8; c++) { v[c] = Gs[tid + 1024 * c]; m = fmaxf(m, v[c]); }
    #pragma unroll
    for (int off = 16; off; off >>= 1) m = fmaxf(m, __shfl_xor_sync(0xffffffffu, m, off));
    if (lane == 0) sm[warp] = m;
    __syncthreads();
    if (tid < 32) {
        float t = sm[tid];
        #pragma unroll
        for (int off = 16; off; off >>= 1) t = fmaxf(t, __shfl_xor_sync(0xffffffffu, t, off));
        if (tid == 0) sm[0] = t;
    }
    __syncthreads();
    m = sm[0];
    __syncthreads();
    float e[8], s = 0.f;
    #pragma unroll
    for (int c = 0; c < 8; c++) { e[c] = expf(v[c] - m); s += e[c]; }
    #pragma unroll
    for (int off = 16; off; off >>= 1) s += __shfl_xor_sync(0xffffffffu, s, off);
    if (lane == 0) sm[warp] = s;
    __syncthreads();
    if (tid < 32) {
        float t = sm[tid];
        #pragma unroll
        for (int off = 16; off; off >>= 1) t += __shfl_xor_sync(0xffffffffu, t, off);
        if (tid == 0) sm[0] = t;
    }
    __syncthreads();
    float inv = 1.f / sm[0];
    #pragma unroll
    for (int c = 0; c < 8; c++) A[tid + 1024 * c] = e[c] * inv;
}

__global__ void eg_partial(const float* __restrict__ A, const float* __restrict__ X,
                           float* __restrict__ P2) {
    int b = blockIdx.x, tid = threadIdx.x;
    float a0 = 0.f, a1 = 0.f;
    for (int r = 0; r < 128; r++) {
        int n = b * 128 + r;
        float a = A[n];
        a0 += a * X[(size_t)n * DH + tid];
        a1 += a * X[(size_t)n * DH + tid + 256];
    }
    P2[b * DH + tid] = a0;
    P2[b * DH + tid + 256] = a1;
}

__global__ void eg_combine(const float* __restrict__ P2, float* __restrict__ eg) {
    int d = threadIdx.x;
    float s = 0.f;
    for (int b = 0; b < 64; b++) s += P2[b * DH + d];
    eg[d] = s;
}

// ---------------- host ------------------------------------------------------
extern "C" void kernel_launch(void* const* d_in, const int* in_sizes, int n_in,
                              void* d_out, int out_size) {
    const float *xo[6], *w1[6];
    int s6[6];
    const float *x_path, *sig_b1, *sig_w2, *sig_b2;

    bool dictOrder = (in_sizes[12] == NPATCH * DIN);
    if (dictOrder) {
        for (int i = 0; i < 6; i++) {
            xo[i] = (const float*)d_in[2 * i];
            w1[i] = (const float*)d_in[2 * i + 1];
            s6[i] = in_sizes[2 * i];
        }
        x_path = (const float*)d_in[12];
        sig_b1 = (const float*)d_in[13];
        sig_w2 = (const float*)d_in[14];
        sig_b2 = (const float*)d_in[15];
    } else {
        for (int i = 0; i < 6; i++) {
            xo[i] = (const float*)d_in[i];
            w1[i] = (const float*)d_in[6 + i];
            s6[i] = in_sizes[i];
        }
        sig_b1 = (const float*)d_in[12];
        sig_w2 = (const float*)d_in[13];
        sig_b2 = (const float*)d_in[14];
        x_path = (const float*)d_in[15];
    }
    const float* fc1_w = (const float*)d_in[16];
    const float* fc1_b = (const float*)d_in[17];
    const float* wh_w  = (const float*)d_in[18];
    const float* wh_b  = (const float*)d_in[19];
    const float* wt_w  = (const float*)d_in[20];
    const float* wt_b  = (const float*)d_in[21];
    const float* l1w   = (const float*)d_in[22];
    const float* l1b   = (const float*)d_in[23];
    const float* l2w   = (const float*)d_in[24];
    const float* l2b   = (const float*)d_in[25];
    const float* aw1   = (const float*)d_in[26];
    const float* ab1   = (const float*)d_in[27];
    const float* aw2   = (const float*)d_in[28];
    const float* ab2   = (const float*)d_in[29];

    float* out     = (float*)d_out;
    float* out_eh2 = out + 6 * HSNN;
    float* out_eg  = out + 6 * HSNN + NPATCH * DH;

    float *H, *EH, *ET, *U, *V, *G1, *PART, *MEAN, *GS, *AB, *P2;
    int* TOPI;
    cudaGetSymbolAddress((void**)&H,    g_H);
    cudaGetSymbolAddress((void**)&EH,   g_EH);
    cudaGetSymbolAddress((void**)&ET,   g_ET);
    cudaGetSymbolAddress((void**)&U,    g_U);
    cudaGetSymbolAddress((void**)&V,    g_V);
    cudaGetSymbolAddress((void**)&G1,   g_G1);
    cudaGetSymbolAddress((void**)&PART, g_PART);
    cudaGetSymbolAddress((void**)&MEAN, g_MEAN);
    cudaGetSymbolAddress((void**)&GS,   g_GS);
    cudaGetSymbolAddress((void**)&AB,   g_AB);
    cudaGetSymbolAddress((void**)&TOPI, g_TOPI);
    cudaGetSymbolAddress((void**)&P2,   g_P2);

    cudaFuncSetAttribute(gemm_tf32<0>, cudaFuncAttributeMaxDynamicSharedMemorySize, GT_SMEM);
    cudaFuncSetAttribute(gemm_tf32<1>, cudaFuncAttributeMaxDynamicSharedMemorySize, GT_SMEM);
    cudaFuncSetAttribute(gemm_tf32<2>, cudaFuncAttributeMaxDynamicSharedMemorySize, GT_SMEM);
    cudaFuncSetAttribute(logits_topk, cudaFuncAttributeMaxDynamicSharedMemorySize, LT_SMEM);

    OmicArgs oa;
    for (int i = 0; i < 6; i++) { oa.x[i] = xo[i]; oa.w1[i] = w1[i]; oa.s[i] = s6[i]; }

    // 1) omic branches -> out[0:1536]
    omic_kernel<<<6, 256>>>(oa, sig_b1, sig_w2, sig_b2, out);

    // 2) h0 = leaky(x_path @ fc1_w^T + b)
    gemm_tf32<1><<<dim3(DH / 64, NPATCH / 128), 256, GT_SMEM>>>(x_path, fc1_w, fc1_b, H, NPATCH, DH, DIN);

    // 3) h = 0.5*(h0 + colmean(h0))
    colsum_partial<<<64, 256>>>(H, PART);
    mean_combine<<<1, 512>>>(PART, MEAN);
    h_update<<<NPATCH * DH / 256, 256>>>(H, MEAN);

    // 4) e_h, e_t
    gemm_tf32<0><<<dim3(DH / 64, NPATCH / 128), 256, GT_SMEM>>>(H, wh_w, wh_b, EH, NPATCH, DH, DH);
    gemm_tf32<0><<<dim3(DH / 64, NPATCH / 128), 256, GT_SMEM>>>(H, wt_w, wt_b, ET, NPATCH, DH, DH);

    // 5) fused tf32-MMA logits + top-16 candidates
    logits_topk<<<NPATCH / 64, 256, LT_SMEM>>>(EH, ET, TOPI);

    // 6) exact rescore + top-6 + kNN aggregation -> U, V
    knn_epi<<<NPATCH, 128>>>(EH, ET, TOPI, U, V);

    // 7) e_h2 = leaky(U@l1^T+b1) + leaky(V@l2^T+b2)  -> out
    gemm_tf32<1><<<dim3(DH / 64, NPATCH / 128), 256, GT_SMEM>>>(U, l1w, l1b, out_eh2, NPATCH, DH, DH);
    gemm_tf32<2><<<dim3(DH / 64, NPATCH / 128), 256, GT_SMEM>>>(V, l2w, l2b, out_eh2, NPATCH, DH, DH);

    // 8) attention readout -> e_g
    gemm_tf32<1><<<dim3(HSNN / 64, NPATCH / 128), 256, GT_SMEM>>>(out_eh2, aw1, ab1, G1, NPATCH, HSNN, DH);
    att_score<<<NPATCH / 8, 256>>>(G1, aw2, ab2, GS);
    softmax_n<<<1, 1024>>>(GS, AB);
    eg_partial<<<64, 256>>>(AB, out_eh2, P2);
    eg_combine<<<1, 512>>>(P2, out_eg);
}

// round 16
// speedup vs baseline: 1.7504x; 1.0163x over previous
#include <cuda_runtime.h>
#include <math.h>

#define NPATCH 8192
#define DIN    384
#define DH     512
#define HSNN   256
#define TOPK   6
#define NCAND  16

typedef unsigned int uint;

__device__ __forceinline__ uint f2tf32(float f) {
    uint u;
    asm("cvt.rna.tf32.f32 %0, %1;" : "=r"(u) : "f"(f));
    return u;
}
__device__ __forceinline__ void mma_tf32(float& c0, float& c1, float& c2, float& c3,
                                         uint a0, uint a1, uint a2, uint a3,
                                         uint b0, uint b1) {
    asm("mma.sync.aligned.m16n8k8.row.col.f32.tf32.tf32.f32 "
        "{%0,%1,%2,%3}, {%4,%5,%6,%7}, {%8,%9}, {%0,%1,%2,%3};"
        : "+f"(c0), "+f"(c1), "+f"(c2), "+f"(c3)
        : "r"(a0), "r"(a1), "r"(a2), "r"(a3), "r"(b0), "r"(b1));
}
// accurate-enough tanh: err ~1e-6, saturates correctly, ~6 instr (2 MUFU)
__device__ __forceinline__ float fast_tanh(float x) {
    float t = __expf(2.f * x);
    return 1.f - __fdividef(2.f, t + 1.f);
}

// ---------------- scratch (static device allocations; no cudaMalloc) --------
__device__ float g_H [NPATCH * DH];
__device__ float g_EH[NPATCH * DH];
__device__ float g_ET[NPATCH * DH];
__device__ float g_U [NPATCH * DH];
__device__ float g_V [NPATCH * DH];
__device__ float g_G1[NPATCH * HSNN];
__device__ float g_PART[64 * DH];
__device__ float g_MEAN[DH];
__device__ float g_GS[NPATCH];
__device__ float g_AB[NPATCH];
__device__ int   g_TOPI[NPATCH * NCAND];
__device__ float g_P2[64 * DH];

// ---------------- omic SNN branches -----------------------------------------
struct OmicArgs {
    const float* x[6];
    const float* w1[6];
    int s[6];
};

__global__ void omic_kernel(OmicArgs oa, const float* __restrict__ sig_b1,
                            const float* __restrict__ sig_w2,
                            const float* __restrict__ sig_b2,
                            float* __restrict__ out) {
    __shared__ float sx[1536];
    __shared__ float h1[HSNN];
    int br = blockIdx.x, tid = threadIdx.x;
    int s = oa.s[br];
    const float* x = oa.x[br];
    for (int j = tid; j < s; j += 256) sx[j] = x[j];
    __syncthreads();
    const float* w = oa.w1[br] + (size_t)tid * s;
    float acc = sig_b1[br * HSNN + tid];
    for (int j = 0; j < s; j++) acc += w[j] * sx[j];
    h1[tid] = acc > 0.f ? acc : expm1f(acc);
    __syncthreads();
    const float* w2 = sig_w2 + (size_t)br * HSNN * HSNN + (size_t)tid * HSNN;
    float acc2 = sig_b2[br * HSNN + tid];
    #pragma unroll 8
    for (int j = 0; j < HSNN; j++) acc2 += w2[j] * h1[j];
    out[br * HSNN + tid] = acc2 > 0.f ? acc2 : expm1f(acc2);
}

// ---------------- 3xTF32 tensor-core NT GEMM (unchanged, passing) ------------
#define GT_AH  0
#define GT_AL  4096
#define GT_BH  8192
#define GT_BL  10240
#define GT_BUF 12288
#define GT_SMEM (2 * GT_BUF * 4)   // 98304 bytes

__device__ __forceinline__ void gt_fill(uint* __restrict__ sm,
                                        const float* __restrict__ A,
                                        const float* __restrict__ B,
                                        int bi, int bj, int k0, int K, int tid) {
    #pragma unroll
    for (int it = 0; it < 4; it++) {
        int s = tid + it * 256;
        int t = s >> 7, q = (s >> 5) & 3, l = s & 31;
        const float* pa = A + (size_t)(bi + t * 16 + (l >> 2)) * K + k0 + q * 8 + (l & 3);
        float a00 = pa[0], a01 = pa[4];
        float a10 = pa[8 * (size_t)K], a11 = pa[8 * (size_t)K + 4];
        uint h00 = f2tf32(a00), h01 = f2tf32(a01), h10 = f2tf32(a10), h11 = f2tf32(a11);
        float l00 = a00 - __uint_as_float(h00);
        float l01 = a01 - __uint_as_float(h01);
        float l10 = a10 - __uint_as_float(h10);
        float l11 = a11 - __uint_as_float(h11);
        int base = ((t * 4 + q) * 32 + l) * 4;
        *(uint4*)&sm[GT_AH + base] = make_uint4(h00, h10, h01, h11);
        *(uint4*)&sm[GT_AL + base] = make_uint4(f2tf32(l00), f2tf32(l10), f2tf32(l01), f2tf32(l11));
    }
    #pragma unroll
    for (int it = 0; it < 4; it++) {
        int s = tid + it * 256;
        int nt = s >> 7, q = (s >> 5) & 3, l = s & 31;
        const float* pb = B + (size_t)(bj + nt * 8 + (l >> 2)) * K + k0 + q * 8 + (l & 3);
        float b0 = pb[0], b1 = pb[4];
        uint h0 = f2tf32(b0), h1 = f2tf32(b1);
        float lo0 = b0 - __uint_as_float(h0);
        float lo1 = b1 - __uint_as_float(h1);
        int base = ((nt * 4 + q) * 32 + l) * 2;
        *(uint2*)&sm[GT_BH + base] = make_uint2(h0, h1);
        *(uint2*)&sm[GT_BL + base] = make_uint2(f2tf32(lo0), f2tf32(lo1));
    }
}

template <int EPI>
__global__ __launch_bounds__(256, 2)
void gemm_tf32(const float* __restrict__ A, const float* __restrict__ B,
               const float* __restrict__ bias, float* __restrict__ C,
               int M, int N, int K) {
    extern __shared__ uint gsm[];
    const int tid = threadIdx.x, lane = tid & 31, wid = tid >> 5;
    const int wm = wid >> 1, wn = wid & 1;
    const int bi = blockIdx.y * 128, bj = blockIdx.x * 64;
    const int nk = K / 32;

    float acc[2][4][4] = {};

    gt_fill(gsm, A, B, bi, bj, 0, K, tid);
    __syncthreads();
    for (int ch = 0; ch < nk; ch++) {
        const uint* cur = gsm + (ch & 1) * GT_BUF;
        if (ch + 1 < nk)
            gt_fill(gsm + ((ch + 1) & 1) * GT_BUF, A, B, bi, bj, (ch + 1) * 32, K, tid);
        #pragma unroll
        for (int q = 0; q < 4; q++) {
            uint4 ah[2], al[2];
            uint2 bh[4], bl[4];
            #pragma unroll
            for (int mt = 0; mt < 2; mt++) {
                int base = (((wm * 2 + mt) * 4 + q) * 32 + lane) * 4;
                ah[mt] = *(const uint4*)&cur[GT_AH + base];
                al[mt] = *(const uint4*)&cur[GT_AL + base];
            }
            #pragma unroll
            for (int nt = 0; nt < 4; nt++) {
                int base = (((wn * 4 + nt) * 4 + q) * 32 + lane) * 2;
                bh[nt] = *(const uint2*)&cur[GT_BH + base];
                bl[nt] = *(const uint2*)&cur[GT_BL + base];
            }
            #pragma unroll
            for (int mt = 0; mt < 2; mt++)
                #pragma unroll
                for (int nt = 0; nt < 4; nt++) {
                    float* c = acc[mt][nt];
                    mma_tf32(c[0], c[1], c[2], c[3],
                             ah[mt].x, ah[mt].y, ah[mt].z, ah[mt].w,
                             bh[nt].x, bh[nt].y);
                    mma_tf32(c[0], c[1], c[2], c[3],
                             ah[mt].x, ah[mt].y, ah[mt].z, ah[mt].w,
                             bl[nt].x, bl[nt].y);
                    mma_tf32(c[0], c[1], c[2], c[3],
                             al[mt].x, al[mt].y, al[mt].z, al[mt].w,
                             bh[nt].x, bh[nt].y);
                }
        }
        __syncthreads();
    }

    #pragma unroll
    for (int mt = 0; mt < 2; mt++) {
        int i0 = bi + wm * 32 + mt * 16 + (lane >> 2);
        #pragma unroll
        for (int nt = 0; nt < 4; nt++) {
            int j0 = bj + wn * 32 + nt * 8 + 2 * (lane & 3);
            float2 bp = *(const float2*)&bias[j0];
            float v0 = acc[mt][nt][0] + bp.x;
            float v1 = acc[mt][nt][1] + bp.y;
            float v2 = acc[mt][nt][2] + bp.x;
            float v3 = acc[mt][nt][3] + bp.y;
            if (EPI >= 1) {
                v0 = v0 >= 0.f ? v0 : 0.01f * v0;
                v1 = v1 >= 0.f ? v1 : 0.01f * v1;
                v2 = v2 >= 0.f ? v2 : 0.01f * v2;
                v3 = v3 >= 0.f ? v3 : 0.01f * v3;
            }
            float* p0 = &C[(size_t)i0 * N + j0];
            float* p1 = &C[(size_t)(i0 + 8) * N + j0];
            if (EPI == 2) {
                float2 o0 = *(float2*)p0, o1 = *(float2*)p1;
                *(float2*)p0 = make_float2(o0.x + v0, o0.y + v1);
                *(float2*)p1 = make_float2(o1.x + v2, o1.y + v3);
            } else {
                *(float2*)p0 = make_float2(v0, v1);
                *(float2*)p1 = make_float2(v2, v3);
            }
        }
    }
}

// ---------------- column mean of H, then h = 0.5*(h + mean) ------------------
__global__ void colsum_partial(const float* __restrict__ H, float* __restrict__ part) {
    int b = blockIdx.x, tid = threadIdx.x;
    const float* base = H + (size_t)b * 128 * DH;
    float a0 = 0.f, a1 = 0.f;
    for (int r = 0; r < 128; r++) {
        a0 += base[r * DH + tid];
        a1 += base[r * DH + tid + 256];
    }
    part[b * DH + tid] = a0;
    part[b * DH + tid + 256] = a1;
}

__global__ void mean_combine(const float* __restrict__ part, float* __restrict__ mean) {
    int d = threadIdx.x;
    float s = 0.f;
    for (int b = 0; b < 64; b++) s += part[b * DH + d];
    mean[d] = s * (1.f / (float)NPATCH);
}

__global__ void h_update(float* __restrict__ H, const float* __restrict__ mean) {
    int idx = blockIdx.x * 256 + threadIdx.x;
    H[idx] = 0.5f * (H[idx] + mean[idx & (DH - 1)]);
}

// ---------------- fused tf32-MMA logits + per-row top-16 candidates ----------
#define LSTRIDE 129
#define LT_AS   (64 * 512)
#define LT_BTILE 4096
#define LT_BS   (2 * LT_BTILE)
#define LT_LS   (64 * LSTRIDE)
#define LT_MV   (64 * 4 * NCAND)
#define LT_SMEM ((LT_AS + LT_BS + LT_LS + 2 * LT_MV) * 4)

__device__ __forceinline__ void fill_b_chunk(uint* __restrict__ dst,
                                             const float* __restrict__ ET,
                                             int bj, int k0, int tid) {
    #pragma unroll
    for (int it = 0; it < 8; it++) {
        int s = tid + it * 256;
        int l = s & 31, q = (s >> 5) & 3, nt = s >> 7;
        int n = bj + nt * 8 + (l >> 2);
        int kk = k0 + q * 8 + (l & 3);
        const float* p = ET + (size_t)n * DH + kk;
        uint2 v = make_uint2(f2tf32(p[0]), f2tf32(p[4]));
        *(uint2*)&dst[s * 2] = v;
    }
}

template <int NC>
__device__ __forceinline__ void topk_insert(float (&lv)[NC], int (&li)[NC],
                                            float v, int ix) {
    if (v > lv[NC - 1]) {
        lv[NC - 1] = v; li[NC - 1] = ix;
        #pragma unroll
        for (int q = NC - 1; q > 0; q--) {
            if (lv[q] > lv[q - 1]) {
                float tf = lv[q]; lv[q] = lv[q - 1]; lv[q - 1] = tf;
                int  t2 = li[q]; li[q] = li[q - 1]; li[q - 1] = t2;
            }
        }
    }
}

__global__ __launch_bounds__(256, 1)
void logits_topk(const float* __restrict__ EH, const float* __restrict__ ET,
                 int* __restrict__ topi) {
    extern __shared__ uint smu[];
    uint*  As = smu;
    uint*  Bs = As + LT_AS;
    float* Ls = (float*)(Bs + LT_BS);
    float* mv = Ls + LT_LS;
    int*   mi = (int*)(mv + LT_MV);
    const int tid = threadIdx.x;
    const int lane = tid & 31;
    const int wid = tid >> 5;
    const int wm = wid >> 2;
    const int wn = wid & 3;
    const int bi = blockIdx.x * 64;

    for (int u = tid; u < 64 * 512; u += 256) {
        int t = u >> 13;
        int v = u & 8191;
        int q = v >> 7;
        int w = v & 127;
        int l = w >> 2, r = w & 3;
        int row = t * 16 + (l >> 2) + (r & 1) * 8;
        int col = q * 8 + (l & 3) + (r >> 1) * 4;
        As[u] = f2tf32(EH[(size_t)(bi + row) * DH + col]);
    }

    float tv[NCAND]; int ti[NCAND];
    #pragma unroll
    for (int k = 0; k < NCAND; k++) { tv[k] = -INFINITY; ti[k] = 0; }
    __syncthreads();

    for (int bj = 0; bj < NPATCH; bj += 128) {
        float acc[2][4][4];
        #pragma unroll
        for (int mt = 0; mt < 2; mt++)
            #pragma unroll
            for (int nt = 0; nt < 4; nt++)
                #pragma unroll
                for (int c = 0; c < 4; c++) acc[mt][nt][c] = 0.f;

        fill_b_chunk(Bs, ET, bj, 0, tid);
        __syncthreads();
        for (int ch = 0; ch < 16; ch++) {
            const uint* cur = Bs + (ch & 1) * LT_BTILE;
            if (ch < 15) fill_b_chunk(Bs + ((ch + 1) & 1) * LT_BTILE, ET, bj, (ch + 1) * 32, tid);
            #pragma unroll
            for (int q = 0; q < 4; q++) {
                int Q = ch * 4 + q;
                uint4 af[2];
                #pragma unroll
                for (int mt = 0; mt < 2; mt++)
                    af[mt] = *(const uint4*)&As[((wm * 2 + mt) * 64 + Q) * 128 + lane * 4];
                uint2 bf[4];
                #pragma unroll
                for (int nt = 0; nt < 4; nt++)
                    bf[nt] = *(const uint2*)&cur[((wn * 4 + nt) * 4 + q) * 64 + lane * 2];
                #pragma unroll
                for (int mt = 0; mt < 2; mt++)
                    #pragma unroll
                    for (int nt = 0; nt < 4; nt++)
                        mma_tf32(acc[mt][nt][0], acc[mt][nt][1], acc[mt][nt][2], acc[mt][nt][3],
                                 af[mt].x, af[mt].y, af[mt].z, af[mt].w,
                                 bf[nt].x, bf[nt].y);
            }
            __syncthreads();
        }
        {
            int g = lane >> 2, c2 = (lane & 3) * 2;
            #pragma unroll
            for (int mt = 0; mt < 2; mt++) {
                int r0 = wm * 32 + mt * 16 + g;
                #pragma unroll
                for (int nt = 0; nt < 4; nt++) {
                    int cb = wn * 32 + nt * 8 + c2;
                    Ls[r0 * LSTRIDE + cb]           = acc[mt][nt][0];
                    Ls[r0 * LSTRIDE + cb + 1]       = acc[mt][nt][1];
                    Ls[(r0 + 8) * LSTRIDE + cb]     = acc[mt][nt][2];
                    Ls[(r0 + 8) * LSTRIDE + cb + 1] = acc[mt][nt][3];
                }
            }
        }
        __syncthreads();
        {
            int srow = tid >> 2, q = tid & 3;
            float lv[NCAND]; int li[NCAND];
            #pragma unroll
            for (int k = 0; k < NCAND; k++) { lv[k] = -INFINITY; li[k] = 0; }
            const float* rp = Ls + srow * LSTRIDE + q * 32;
            for (int t = 0; t < 32; t++) {
                int cc = (t + q * 8) & 31;
                topk_insert<NCAND>(lv, li, rp[cc], bj + q * 32 + cc);
            }
            #pragma unroll
            for (int k = 0; k < NCAND; k++) {
                mv[(srow * 4 + q) * NCAND + k] = lv[k];
                mi[(srow * 4 + q) * NCAND + k] = li[k];
            }
        }
        __syncthreads();
        if (tid < 64) {
            for (int s = 0; s < 4 * NCAND; s++)
                topk_insert<NCAND>(tv, ti, mv[tid * 4 * NCAND + s], mi[tid * 4 * NCAND + s]);
        }
    }
    if (tid < 64) {
        #pragma unroll
        for (int k = 0; k < NCAND; k++)
            topi[(size_t)(bi + tid) * NCAND + k] = ti[k];
    }
}

// ---------------- per-row kNN: warp-per-row, exact rescore + top-6 + agg -----
#define KNN_ROWS 8
__global__ __launch_bounds__(256)
void knn_epi(const float* __restrict__ EH, const float* __restrict__ ET,
             const int* __restrict__ topi,
             float* __restrict__ U, float* __restrict__ V) {
    __shared__ float sv[KNN_ROWS][NCAND];
    __shared__ float sn[KNN_ROWS][NCAND];
    __shared__ int   si[KNN_ROWS][NCAND];
    const int w = threadIdx.x >> 5, lane = threadIdx.x & 31;
    const int i = blockIdx.x * KNN_ROWS + w;
    const float scale = 0.04419417382415922f;  // 512^-0.5

    const float4* ehp = (const float4*)(EH + (size_t)i * DH);
    float4 eh4[4];
    #pragma unroll
    for (int cc = 0; cc < 4; cc++) eh4[cc] = ehp[lane + 32 * cc];

    int myidx = topi[(size_t)i * NCAND + (lane & 15)];

    // pass 1: exact logit + neighbor sum for 16 candidates
    #pragma unroll
    for (int c = 0; c < NCAND; c++) {
        int ix = __shfl_sync(0xffffffffu, myidx, c);
        const float4* et = (const float4*)(ET + (size_t)ix * DH);
        float sL = 0.f, sN = 0.f;
        #pragma unroll
        for (int cc = 0; cc < 4; cc++) {
            float4 nb = et[lane + 32 * cc];
            sL += eh4[cc].x * nb.x + eh4[cc].y * nb.y + eh4[cc].z * nb.z + eh4[cc].w * nb.w;
            sN += nb.x + nb.y + nb.z + nb.w;
        }
        #pragma unroll
        for (int off = 16; off; off >>= 1) {
            sL += __shfl_down_sync(0xffffffffu, sL, off);
            sN += __shfl_down_sync(0xffffffffu, sN, off);
        }
        if (lane == 0) { sv[w][c] = sL * scale; sn[w][c] = sN; si[w][c] = ix; }
    }
    __syncwarp();

    float cval[NCAND]; int cidx[NCAND];
    #pragma unroll
    for (int c = 0; c < NCAND; c++) { cval[c] = sv[w][c]; cidx[c] = si[w][c]; }

    // exact top-6 of 16 (value desc, lower index on ties), same on all lanes
    float vals[TOPK], sN6[TOPK];
    int sidx[TOPK];
    unsigned used = 0;
    #pragma unroll
    for (int k = 0; k < TOPK; k++) {
        float best = -INFINITY; int bc = -1, bix = 0x7fffffff;
        #pragma unroll
        for (int c = 0; c < NCAND; c++) {
            if (!(used & (1u << c))) {
                float v = cval[c];
                if (v > best || (v == best && cidx[c] < bix)) { best = v; bc = c; bix = cidx[c]; }
            }
        }
        used |= 1u << bc;
        vals[k] = best;
        sidx[k] = bix;
        sN6[k] = sn[w][bc];
    }

    float m = vals[0];
    #pragma unroll
    for (int k = 1; k < TOPK; k++) m = fmaxf(m, vals[k]);
    float se = 0.f, p[TOPK];
    #pragma unroll
    for (int k = 0; k < TOPK; k++) { p[k] = __expf(vals[k] - m); se += p[k]; }
    float inv = __fdividef(1.f, se);
    #pragma unroll
    for (int k = 0; k < TOPK; k++) p[k] *= inv;

    // pass 2: gate sums (arg = (2-p)*eh + p*nb)
    float gate6[TOPK];
    #pragma unroll
    for (int k = 0; k < TOPK; k++) {
        const float4* et = (const float4*)(ET + (size_t)sidx[k] * DH);
        float q2 = 2.f - p[k], pk = p[k];
        float sG = 0.f;
        #pragma unroll
        for (int cc = 0; cc < 4; cc++) {
            float4 nb = et[lane + 32 * cc];
            sG += fast_tanh(q2 * eh4[cc].x + pk * nb.x);
            sG += fast_tanh(q2 * eh4[cc].y + pk * nb.y);
            sG += fast_tanh(q2 * eh4[cc].z + pk * nb.z);
            sG += fast_tanh(q2 * eh4[cc].w + pk * nb.w);
        }
        #pragma unroll
        for (int off = 16; off; off >>= 1)
            sG += __shfl_xor_sync(0xffffffffu, sG, off);
        gate6[k] = sG;
    }

    float ka[TOPK], kp[TOPK];
    #pragma unroll
    for (int k = 0; k < TOPK; k++) ka[k] = sN6[k] * gate6[k];
    m = ka[0];
    #pragma unroll
    for (int k = 1; k < TOPK; k++) m = fmaxf(m, ka[k]);
    se = 0.f;
    #pragma unroll
    for (int k = 0; k < TOPK; k++) { kp[k] = __expf(ka[k] - m); se += kp[k]; }
    inv = __fdividef(1.f, se);
    #pragma unroll
    for (int k = 0; k < TOPK; k++) kp[k] *= inv;

    // pass 3: e_Nh accumulate + store U, V
    float4 enh[4];
    #pragma unroll
    for (int cc = 0; cc < 4; cc++) enh[cc] = make_float4(0.f, 0.f, 0.f, 0.f);
    #pragma unroll
    for (int k = 0; k < TOPK; k++) {
        const float4* et = (const float4*)(ET + (size_t)sidx[k] * DH);
        float kpk = kp[k];
        #pragma unroll
        for (int cc = 0; cc < 4; cc++) {
            float4 nb = et[lane + 32 * cc];
            enh[cc].x += kpk * nb.x;
            enh[cc].y += kpk * nb.y;
            enh[cc].z += kpk * nb.z;
            enh[cc].w += kpk * nb.w;
        }
    }
    float4* Up = (float4*)(U + (size_t)i * DH);
    float4* Vp = (float4*)(V + (size_t)i * DH);
    #pragma unroll
    for (int cc = 0; cc < 4; cc++) {
        float4 e = eh4[cc], n = enh[cc];
        Up[lane + 32 * cc] = make_float4(e.x + n.x, e.y + n.y, e.z + n.z, e.w + n.w);
        Vp[lane + 32 * cc] = make_float4(e.x * n.x, e.y * n.y, e.z * n.z, e.w * n.w);
    }
}

// ---------------- attention readout ------------------------------------------
__global__ void att_score(const float* __restrict__ G1, const float* __restrict__ aw2,
                          const float* __restrict__ ab2, float* __restrict__ Gs) {
    int warp = threadIdx.x >> 5, lane = threadIdx.x & 31;
    int row = blockIdx.x * 8 + warp;
    float s = 0.f;
    #pragma unroll
    for (int c = 0; c < 8; c++) {
        int j = lane + 32 * c;
        s += G1[(size_t)row * HSNN + j] * aw2[j];
    }
    #pragma unroll
    for (int off = 16; off; off >>= 1) s += __shfl_down_sync(0xffffffffu, s, off);
    if (lane == 0) Gs[row] = s + ab2[0];
}

__global__ void softmax_n(const float* __restrict__ Gs, float* __restrict__ A) {
    __shared__ float sm[32];
    int tid = threadIdx.x;
    int lane = tid & 31, warp = tid >> 5;
    float v[8], m = -INFINITY;
    #pragma unroll
    for (int c = 0; c < 8; c++) { v[c] = Gs[tid + 1024 * c]; m = fmaxf(m, v[c]); }
    #pragma unroll
    for (int off = 16; off; off >>= 1) m = fmaxf(m, __shfl_xor_sync(0xffffffffu, m, off));
    if (lane == 0) sm[warp] = m;
    __syncthreads();
    if (tid < 32) {
        float t = sm[tid];
        #pragma unroll
        for (int off = 16; off; off >>= 1) t = fmaxf(t, __shfl_xor_sync(0xffffffffu, t, off));
        if (tid == 0) sm[0] = t;
    }
    __syncthreads();
    m = sm[0];
    __syncthreads();
    float e[8], s = 0.f;
    #pragma unroll
    for (int c = 0; c < 8; c++) { e[c] = expf(v[c] - m); s += e[c]; }
    #pragma unroll
    for (int off = 16; off; off >>= 1) s += __shfl_xor_sync(0xffffffffu, s, off);
    if (lane == 0) sm[warp] = s;
    __syncthreads();
    if (tid < 32) {
        float t = sm[tid];
        #pragma unroll
        for (int off = 16; off; off >>= 1) t += __shfl_xor_sync(0xffffffffu, t, off);
        if (tid == 0) sm[0] = t;
    }
    __syncthreads();
    float inv = 1.f / sm[0];
    #pragma unroll
    for (int c = 0; c < 8; c++) A[tid + 1024 * c] = e[c] * inv;
}

__global__ void eg_partial(const float* __restrict__ A, const float* __restrict__ X,
                           float* __restrict__ P2) {
    int b = blockIdx.x, tid = threadIdx.x;
    float a0 = 0.f, a1 = 0.f;
    for (int r = 0; r < 128; r++) {
        int n = b * 128 + r;
        float a = A[n];
        a0 += a * X[(size_t)n * DH + tid];
        a1 += a * X[(size_t)n * DH + tid + 256];
    }
    P2[b * DH + tid] = a0;
    P2[b * DH + tid + 256] = a1;
}

__global__ void eg_combine(const float* __restrict__ P2, float* __restrict__ eg) {
    int d = threadIdx.x;
    float s = 0.f;
    for (int b = 0; b < 64; b++) s += P2[b * DH + d];
    eg[d] = s;
}

// ---------------- host ------------------------------------------------------
extern "C" void kernel_launch(void* const* d_in, const int* in_sizes, int n_in,
                              void* d_out, int out_size) {
    const float *xo[6], *w1[6];
    int s6[6];
    const float *x_path, *sig_b1, *sig_w2, *sig_b2;

    bool dictOrder = (in_sizes[12] == NPATCH * DIN);
    if (dictOrder) {
        for (int i = 0; i < 6; i++) {
            xo[i] = (const float*)d_in[2 * i];
            w1[i] = (const float*)d_in[2 * i + 1];
            s6[i] = in_sizes[2 * i];
        }
        x_path = (const float*)d_in[12];
        sig_b1 = (const float*)d_in[13];
        sig_w2 = (const float*)d_in[14];
        sig_b2 = (const float*)d_in[15];
    } else {
        for (int i = 0; i < 6; i++) {
            xo[i] = (const float*)d_in[i];
            w1[i] = (const float*)d_in[6 + i];
            s6[i] = in_sizes[i];
        }
        sig_b1 = (const float*)d_in[12];
        sig_w2 = (const float*)d_in[13];
        sig_b2 = (const float*)d_in[14];
        x_path = (const float*)d_in[15];
    }
    const float* fc1_w = (const float*)d_in[16];
    const float* fc1_b = (const float*)d_in[17];
    const float* wh_w  = (const float*)d_in[18];
    const float* wh_b  = (const float*)d_in[19];
    const float* wt_w  = (const float*)d_in[20];
    const float* wt_b  = (const float*)d_in[21];
    const float* l1w   = (const float*)d_in[22];
    const float* l1b   = (const float*)d_in[23];
    const float* l2w   = (const float*)d_in[24];
    const float* l2b   = (const float*)d_in[25];
    const float* aw1   = (const float*)d_in[26];
    const float* ab1   = (const float*)d_in[27];
    const float* aw2   = (const float*)d_in[28];
    const float* ab2   = (const float*)d_in[29];

    float* out     = (float*)d_out;
    float* out_eh2 = out + 6 * HSNN;
    float* out_eg  = out + 6 * HSNN + NPATCH * DH;

    float *H, *EH, *ET, *U, *V, *G1, *PART, *MEAN, *GS, *AB, *P2;
    int* TOPI;
    cudaGetSymbolAddress((void**)&H,    g_H);
    cudaGetSymbolAddress((void**)&EH,   g_EH);
    cudaGetSymbolAddress((void**)&ET,   g_ET);
    cudaGetSymbolAddress((void**)&U,    g_U);
    cudaGetSymbolAddress((void**)&V,    g_V);
    cudaGetSymbolAddress((void**)&G1,   g_G1);
    cudaGetSymbolAddress((void**)&PART, g_PART);
    cudaGetSymbolAddress((void**)&MEAN, g_MEAN);
    cudaGetSymbolAddress((void**)&GS,   g_GS);
    cudaGetSymbolAddress((void**)&AB,   g_AB);
    cudaGetSymbolAddress((void**)&TOPI, g_TOPI);
    cudaGetSymbolAddress((void**)&P2,   g_P2);

    cudaFuncSetAttribute(gemm_tf32<0>, cudaFuncAttributeMaxDynamicSharedMemorySize, GT_SMEM);
    cudaFuncSetAttribute(gemm_tf32<1>, cudaFuncAttributeMaxDynamicSharedMemorySize, GT_SMEM);
    cudaFuncSetAttribute(gemm_tf32<2>, cudaFuncAttributeMaxDynamicSharedMemorySize, GT_SMEM);
    cudaFuncSetAttribute(logits_topk, cudaFuncAttributeMaxDynamicSharedMemorySize, LT_SMEM);

    OmicArgs oa;
    for (int i = 0; i < 6; i++) { oa.x[i] = xo[i]; oa.w1[i] = w1[i]; oa.s[i] = s6[i]; }

    // 1) omic branches -> out[0:1536]
    omic_kernel<<<6, 256>>>(oa, sig_b1, sig_w2, sig_b2, out);

    // 2) h0 = leaky(x_path @ fc1_w^T + b)
    gemm_tf32<1><<<dim3(DH / 64, NPATCH / 128), 256, GT_SMEM>>>(x_path, fc1_w, fc1_b, H, NPATCH, DH, DIN);

    // 3) h = 0.5*(h0 + colmean(h0))
    colsum_partial<<<64, 256>>>(H, PART);
    mean_combine<<<1, 512>>>(PART, MEAN);
    h_update<<<NPATCH * DH / 256, 256>>>(H, MEAN);

    // 4) e_h, e_t
    gemm_tf32<0><<<dim3(DH / 64, NPATCH / 128), 256, GT_SMEM>>>(H, wh_w, wh_b, EH, NPATCH, DH, DH);
    gemm_tf32<0><<<dim3(DH / 64, NPATCH / 128), 256, GT_SMEM>>>(H, wt_w, wt_b, ET, NPATCH, DH, DH);

    // 5) fused tf32-MMA logits + top-16 candidates
    logits_topk<<<NPATCH / 64, 256, LT_SMEM>>>(EH, ET, TOPI);

    // 6) warp-per-row exact rescore + top-6 + kNN aggregation -> U, V
    knn_epi<<<NPATCH / KNN_ROWS, 256>>>(EH, ET, TOPI, U, V);

    // 7) e_h2 = leaky(U@l1^T+b1) + leaky(V@l2^T+b2)  -> out
    gemm_tf32<1><<<dim3(DH / 64, NPATCH / 128), 256, GT_SMEM>>>(U, l1w, l1b, out_eh2, NPATCH, DH, DH);
    gemm_tf32<2><<<dim3(DH / 64, NPATCH / 128), 256, GT_SMEM>>>(V, l2w, l2b, out_eh2, NPATCH, DH, DH);

    // 8) attention readout -> e_g
    gemm_tf32<1><<<dim3(HSNN / 64, NPATCH / 128), 256, GT_SMEM>>>(out_eh2, aw1, ab1, G1, NPATCH, HSNN, DH);
    att_score<<<NPATCH / 8, 256>>>(G1, aw2, ab2, GS);
    softmax_n<<<1, 1024>>>(GS, AB);
    eg_partial<<<64, 256>>>(AB, out_eh2, P2);
    eg_combine<<<1, 512>>>(P2, out_eg);
}